// round 13
// baseline (speedup 1.0000x reference)
#include <cuda_runtime.h>
#include <cuda_bf16.h>
#include <math.h>
#include <stdint.h>

#define GN 16384
#define HID 128
#define FB 257
#define FDIM 512
#define EDIM 256
#define FEPS 1.1920929e-07f

typedef __nv_bfloat16 bf16;

// ---------------- scratch (__device__ globals) ----------------
static __device__ float d_twr[256], d_twi[256];
static __device__ float d_mag[GN * FB], d_cosF[GN * FB], d_sinF[GN * FB];
static __device__ float d_mask1[GN * FB];
static __device__ float d_enc[(size_t)GN * EDIM];
static __device__ float d_sscrA[(size_t)GN * 512], d_sscrB[(size_t)GN * 512];

// bf16 hi/lo activation buffers
#define KMAG 320
static __device__ bf16 d_magH[(size_t)GN * KMAG], d_magL[(size_t)GN * KMAG];
static __device__ bf16 d_y1H[(size_t)GN * 512],  d_y1L[(size_t)GN * 512];
static __device__ bf16 d_encnH[(size_t)GN * 256], d_encnL[(size_t)GN * 256];
static __device__ bf16 d_mulH[(size_t)GN * 256],  d_mulL[(size_t)GN * 256];
static __device__ bf16 d_h1aH[GN * HID], d_h1aL[GN * HID];
static __device__ bf16 d_h2aH[GN * HID], d_h2aL[GN * HID];
static __device__ bf16 d_h1bH[GN * HID], d_h1bL[GN * HID];
static __device__ bf16 d_h2bH[GN * HID], d_h2bL[GN * HID];
static __device__ bf16 d_hnAH[GN * HID], d_hnAL[GN * HID];
static __device__ bf16 d_hnBH[GN * HID], d_hnBL[GN * HID];

// weight pool (padded bf16 hi/lo), element offsets
#define WP_W1A   0          // wih1   512x320
#define WP_W1B   163840     // whh1   512x128
#define WP_W2A   229376     // wih2   512x128
#define WP_W2B   294912     // whh2   512x128
#define WP_DW1   360448     // dw1    384x128
#define WP_ENC   409600     // enc_w  256x512
#define WP_S1A   540672     // s2_wih1 512x256
#define WP_S1B   671744     // s2_whh1 512x128
#define WP_S2A   737280     // s2_wih2 512x128
#define WP_S2B   802816     // s2_whh2 512x128
#define WP_DW2   868352     // s2_dw  256x128
#define WP_DEC   901120     // dec_w  512x256
#define WP_TOT   1032192
static __device__ bf16 d_wpH[WP_TOT], d_wpL[WP_TOT];

__device__ __forceinline__ float sigm(float x) { return 1.f / (1.f + __expf(-x)); }
__device__ __forceinline__ float tfast(float x) { return 2.f / (1.f + __expf(-2.f * x)) - 1.f; }

__device__ __forceinline__ void split2(float v, bf16* ph, bf16* pl) {
    bf16 h = __float2bfloat16(v);
    *ph = h;
    *pl = __float2bfloat16(v - __bfloat162float(h));
}

// ---------------- PTX helpers ----------------
__device__ __forceinline__ void cp16(uint32_t dst, const void* src) {
    asm volatile("cp.async.cg.shared.global [%0], [%1], 16;" :: "r"(dst), "l"(src));
}
__device__ __forceinline__ void ldm4(uint32_t* r, uint32_t a) {
    asm volatile("ldmatrix.sync.aligned.m8n8.x4.shared.b16 {%0,%1,%2,%3}, [%4];"
                 : "=r"(r[0]), "=r"(r[1]), "=r"(r[2]), "=r"(r[3]) : "r"(a));
}
__device__ __forceinline__ void mma16816(float* c, const uint32_t* a, const uint32_t* b) {
    asm volatile(
        "mma.sync.aligned.m16n8k16.row.col.f32.bf16.bf16.f32 "
        "{%0,%1,%2,%3}, {%4,%5,%6,%7}, {%8,%9}, {%0,%1,%2,%3};"
        : "+f"(c[0]), "+f"(c[1]), "+f"(c[2]), "+f"(c[3])
        : "r"(a[0]), "r"(a[1]), "r"(a[2]), "r"(a[3]), "r"(b[0]), "r"(b[1]));
}

// ---------------- twiddles ----------------
__global__ void init_tw() {
    int k = threadIdx.x;
    float s, c;
    sincospif(-(float)k / 256.f, &s, &c);
    d_twr[k] = c;
    d_twi[k] = s;
}

// ---------------- forward rFFT (512) + mag/cos/sin ----------------
__global__ void fft_fwd(const float* __restrict__ x,
                        float* __restrict__ mag, float* __restrict__ cosF, float* __restrict__ sinF,
                        bf16* __restrict__ magH, bf16* __restrict__ magL) {
    __shared__ float re[512], im[512];
    int n = blockIdx.x;
    int t = threadIdx.x;
    const float* xr = x + (size_t)n * 512;
    for (int i = t; i < 512; i += 256) {
        int p = __brev(i) >> 23;
        re[i] = xr[p];
        im[i] = 0.f;
    }
    __syncthreads();
#pragma unroll
    for (int s = 1; s <= 9; ++s) {
        int half = 1 << (s - 1);
        int grp = t >> (s - 1);
        int j = t & (half - 1);
        int idx = (grp << s) + j;
        int twidx = j << (9 - s);
        float wr = d_twr[twidx], wi = d_twi[twidx];
        float ur = re[idx], ui = im[idx];
        float vr = re[idx + half], vi = im[idx + half];
        float tr = vr * wr - vi * wi;
        float ti = vr * wi + vi * wr;
        re[idx] = ur + tr;
        im[idx] = ui + ti;
        re[idx + half] = ur - tr;
        im[idx + half] = ui - ti;
        __syncthreads();
    }
    for (int k = t; k < KMAG; k += 256) {
        size_t op = (size_t)n * KMAG + k;
        if (k < FB) {
            float r = re[k], i2 = im[k];
            float mg = sqrtf(fmaxf(r * r + i2 * i2, FEPS));
            float rp = r + FEPS, ip = i2 + FEPS;
            float h = sqrtf(rp * rp + ip * ip);
            float inv = (h > 0.f) ? (1.f / h) : 0.f;
            size_t o = (size_t)n * FB + k;
            mag[o] = mg;
            cosF[o] = (h > 0.f) ? rp * inv : 1.f;
            sinF[o] = ip * inv;
            split2(mg, &magH[op], &magL[op]);
        } else {
            magH[op] = __float2bfloat16(0.f);
            magL[op] = __float2bfloat16(0.f);
        }
    }
}

// ---------------- apply mask + inverse rFFT -> y1 (bf16 hi/lo) ----------------
__global__ void ifft_apply(const float* __restrict__ mask, const float* __restrict__ mag,
                           const float* __restrict__ cosF, const float* __restrict__ sinF,
                           bf16* __restrict__ yH, bf16* __restrict__ yL) {
    __shared__ float re[512], im[512];
    __shared__ float xr[FB], xi[FB];
    int n = blockIdx.x;
    int t = threadIdx.x;
    for (int k = t; k < FB; k += 256) {
        size_t o = (size_t)n * FB + k;
        float em = mask[o] * mag[o];
        xr[k] = em * cosF[o];
        xi[k] = em * sinF[o];
    }
    __syncthreads();
    for (int i = t; i < 512; i += 256) {
        int p = __brev(i) >> 23;
        if (p <= 256) { re[i] = xr[p]; im[i] = xi[p]; }
        else          { re[i] = xr[512 - p]; im[i] = -xi[512 - p]; }
    }
    __syncthreads();
#pragma unroll
    for (int s = 1; s <= 9; ++s) {
        int half = 1 << (s - 1);
        int grp = t >> (s - 1);
        int j = t & (half - 1);
        int idx = (grp << s) + j;
        int twidx = j << (9 - s);
        float wr = d_twr[twidx], wi = -d_twi[twidx];
        float ur = re[idx], ui = im[idx];
        float vr = re[idx + half], vi = im[idx + half];
        float tr = vr * wr - vi * wi;
        float ti = vr * wi + vi * wr;
        re[idx] = ur + tr;
        im[idx] = ui + ti;
        re[idx + half] = ur - tr;
        im[idx + half] = ui - ti;
        __syncthreads();
    }
    for (int i = t; i < 512; i += 256) {
        size_t o = (size_t)n * 512 + i;
        split2(re[i] * (1.f / 512.f), &yH[o], &yL[o]);
    }
}

// ---------------- fused weight conversion: all 12 weights in one launch ----------------
// ilv=1: gate-interleave rows (dest row c=4j+g takes source row g*128+j)
struct WConvArgs {
    const float* src[12];
    int M[12], K[12], Kpad[12], off[12], ilv[12];
};

__global__ void convW_all(WConvArgs a) {
    int idx = blockIdx.x * 256 + threadIdx.x;
    if (idx >= WP_TOT) return;
    int s = 0;
#pragma unroll
    for (int i = 1; i < 12; i++)
        if (idx >= a.off[i]) s = i;
    int local = idx - a.off[s];
    int Kp = a.Kpad[s];
    int row = local / Kp, k = local - row * Kp;
    int srow = a.ilv[s] ? (((row & 3) << 7) | (row >> 2)) : row;
    float v = (srow < a.M[s] && k < a.K[s]) ? a.src[s][(size_t)srow * a.K[s] + k] : 0.f;
    split2(v, &d_wpH[idx], &d_wpL[idx]);
}

// ================= mma.sync bf16 split-precision GEMM =================
// C[GN,M] = A1@W1^T (+ A2@W2^T) + b1 (+ b2).
// MODE 0: linear -> C.  MODE 1: sigmoid -> C.
// MODE 2: sigmoid * xtra -> (oH,oL) bf16 split.
// MODE 3: fused LSTM cell (gate-interleaved weights, M=512 full tiles):
//   xtra = state pair base (c at [n*256+2j+1]), C = out state pair, oH/oL = dense h split.
// Tile 128x128, BK=64, 256 threads (8 warps 4m x 2n), 2-stage cp.async pipeline.
#define STG 65536u
#define SMEM_BYTES (2 * 65536)

__device__ __forceinline__ void load_stage(uint32_t sb,
                                           const bf16* __restrict__ Ah, const bf16* __restrict__ Al,
                                           const bf16* __restrict__ Wh, const bf16* __restrict__ Wl,
                                           int Kp, int k0, int row0, int col0, int tid) {
#pragma unroll
    for (int it = 0; it < 4; it++) {
        int idx = it * 256 + tid;
        int r = idx >> 3, c = idx & 7;
        uint32_t off = (uint32_t)(r * 128 + ((c ^ (r & 7)) * 16));
        size_t ga = (size_t)(row0 + r) * Kp + k0 + c * 8;
        size_t gw = (size_t)(col0 + r) * Kp + k0 + c * 8;
        cp16(sb + off,            Ah + ga);
        cp16(sb + 16384u + off,   Al + ga);
        cp16(sb + 32768u + off,   Wh + gw);
        cp16(sb + 49152u + off,   Wl + gw);
    }
}

template <int MODE>
__global__ void __launch_bounds__(256) mma_gemm(
    const bf16* __restrict__ aH, const bf16* __restrict__ aL, int K1p,
    const bf16* __restrict__ a2H, const bf16* __restrict__ a2L, int K2p,
    const bf16* __restrict__ w1H, const bf16* __restrict__ w1L,
    const bf16* __restrict__ w2H, const bf16* __restrict__ w2L,
    const float* __restrict__ b1, const float* __restrict__ b2,
    float* __restrict__ C, int M,
    const float* __restrict__ xtra, bf16* __restrict__ oH, bf16* __restrict__ oL) {
    extern __shared__ __align__(1024) char smem[];
    uint32_t sbase = (uint32_t)__cvta_generic_to_shared(smem);
    int tid = threadIdx.x;
    int lane = tid & 31, wid = tid >> 5;
    int wm = wid & 3, wn = wid >> 2;
    int row0 = blockIdx.y * 128, col0 = blockIdx.x * 128;

    float acc[2][8][4];
#pragma unroll
    for (int m = 0; m < 2; m++)
#pragma unroll
        for (int n = 0; n < 8; n++)
#pragma unroll
            for (int k = 0; k < 4; k++) acc[m][n][k] = 0.f;

    int NC1 = K1p >> 6;
    int NC2 = a2H ? (K2p >> 6) : 0;
    int NC = NC1 + NC2;

    auto seg = [&](int tt, const bf16*& Ah, const bf16*& Al, const bf16*& Wh, const bf16*& Wl,
                   int& Kp, int& k0) {
        if (tt < NC1) { Ah = aH;  Al = aL;  Wh = w1H; Wl = w1L; Kp = K1p; k0 = tt * 64; }
        else          { Ah = a2H; Al = a2L; Wh = w2H; Wl = w2L; Kp = K2p; k0 = (tt - NC1) * 64; }
    };

    // prologue: stage 0
    {
        const bf16 *Ah, *Al, *Wh, *Wl; int Kp, k0;
        seg(0, Ah, Al, Wh, Wl, Kp, k0);
        load_stage(sbase, Ah, Al, Wh, Wl, Kp, k0, row0, col0, tid);
        asm volatile("cp.async.commit_group;");
    }

    for (int ch = 0; ch < NC; ch++) {
        if (ch + 1 < NC) {
            const bf16 *Ah, *Al, *Wh, *Wl; int Kp, k0;
            seg(ch + 1, Ah, Al, Wh, Wl, Kp, k0);
            load_stage(sbase + (uint32_t)((ch + 1) & 1) * STG, Ah, Al, Wh, Wl, Kp, k0, row0, col0, tid);
            asm volatile("cp.async.commit_group;");
            asm volatile("cp.async.wait_group 1;");
        } else {
            asm volatile("cp.async.wait_group 0;");
        }
        __syncthreads();

        uint32_t sb = sbase + (uint32_t)(ch & 1) * STG;
#pragma unroll
        for (int s = 0; s < 4; s++) {
            uint32_t ah[2][4], al[2][4];
#pragma unroll
            for (int m = 0; m < 2; m++) {
                int row = wm * 32 + m * 16 + (lane & 15);
                int chunk = s * 2 + (lane >> 4);
                uint32_t off = (uint32_t)(row * 128 + ((chunk ^ (row & 7)) * 16));
                ldm4(ah[m], sb + off);
                ldm4(al[m], sb + 16384u + off);
            }
            uint32_t bh[4][4], bl[4][4];
#pragma unroll
            for (int p = 0; p < 4; p++) {
                int rw = wn * 64 + p * 16 + (lane & 7) + ((lane >> 4) & 1) * 8;
                int chunk = s * 2 + ((lane >> 3) & 1);
                uint32_t off = (uint32_t)(rw * 128 + ((chunk ^ (rw & 7)) * 16));
                ldm4(bh[p], sb + 32768u + off);
                ldm4(bl[p], sb + 49152u + off);
            }
#pragma unroll
            for (int m = 0; m < 2; m++)
#pragma unroll
                for (int p = 0; p < 4; p++)
#pragma unroll
                    for (int h = 0; h < 2; h++) {
                        float* cc = acc[m][p * 2 + h];
                        mma16816(cc, ah[m], &bh[p][h * 2]);
                        mma16816(cc, ah[m], &bl[p][h * 2]);
                        mma16816(cc, al[m], &bh[p][h * 2]);
                    }
        }
        __syncthreads();
    }

    // ---------------- epilogue ----------------
    if (MODE == 3) {
        // fused LSTM cell; all tiles full (M=512). Gate layout: col = 4j + g.
#pragma unroll
        for (int m = 0; m < 2; m++) {
#pragma unroll
            for (int n = 0; n < 8; n++) {
                float* cc = acc[m][n];
                int r0 = row0 + wm * 32 + m * 16 + (lane >> 2);
                int c0 = col0 + wn * 64 + n * 8 + (lane & 3) * 2;
                float v[4];
#pragma unroll
                for (int e = 0; e < 4; e++) {
                    int col = c0 + (e & 1);
                    int bc = ((col & 3) << 7) | (col >> 2);
                    v[e] = cc[e] + __ldg(b1 + bc) + __ldg(b2 + bc);
                }
                float p[4];
#pragma unroll
                for (int e = 0; e < 4; e++)
                    p[e] = __shfl_xor_sync(0xffffffffu, v[e], 1);
                if (lane & 1) {
                    // this lane holds gates (g,o); partner holds (i,f)
                    int j = c0 >> 2;
#pragma unroll
                    for (int hh = 0; hh < 2; hh++) {
                        int row = r0 + hh * 8;
                        float vi = p[hh * 2], vf = p[hh * 2 + 1];
                        float vg = v[hh * 2], vo = v[hh * 2 + 1];
                        float cprev = __ldg(xtra + (size_t)row * 256 + 2 * j + 1);
                        float c2 = sigm(vf) * cprev + sigm(vi) * tfast(vg);
                        float h2 = sigm(vo) * tfast(c2);
                        C[(size_t)row * 256 + 2 * j] = h2;
                        C[(size_t)row * 256 + 2 * j + 1] = c2;
                        split2(h2, &oH[(size_t)row * 128 + j], &oL[(size_t)row * 128 + j]);
                    }
                }
            }
        }
        return;
    }
#pragma unroll
    for (int m = 0; m < 2; m++) {
#pragma unroll
        for (int n = 0; n < 8; n++) {
            float* cc = acc[m][n];
            int r0 = row0 + wm * 32 + m * 16 + (lane >> 2);
            int c0 = col0 + wn * 64 + n * 8 + (lane & 3) * 2;
#pragma unroll
            for (int e = 0; e < 4; e++) {
                int row = r0 + (e >> 1) * 8;
                int col = c0 + (e & 1);
                if (col < M) {
                    float v = cc[e];
                    if (b1) v += __ldg(b1 + col);
                    if (b2) v += __ldg(b2 + col);
                    size_t oidx = (size_t)row * M + col;
                    if (MODE == 0) {
                        C[oidx] = v;
                    } else if (MODE == 1) {
                        C[oidx] = sigm(v);
                    } else {
                        float r = sigm(v) * __ldg(xtra + oidx);
                        split2(r, &oH[oidx], &oL[oidx]);
                    }
                }
            }
        }
    }
}

// ---------------- extract h from interleaved states -> bf16 hi/lo ----------------
__global__ void extract_h(const float* __restrict__ s1, const float* __restrict__ s2) {
    int idx = blockIdx.x * 256 + threadIdx.x;
    int n = idx >> 7, j = idx & 127;
    size_t o0 = (size_t)n * 256 + 2 * j;
    size_t o1 = ((size_t)GN + n) * 256 + 2 * j;
    split2(s1[o0], &d_h1aH[idx], &d_h1aL[idx]);
    split2(s1[o1], &d_h2aH[idx], &d_h2aL[idx]);
    split2(s2[o0], &d_h1bH[idx], &d_h1bL[idx]);
    split2(s2[o1], &d_h2bH[idx], &d_h2bL[idx]);
}

// ---------------- layernorm over 256 -> bf16 hi/lo ----------------
__global__ void ln_kernel(const float* __restrict__ enc, const float* __restrict__ gamma,
                          const float* __restrict__ beta,
                          bf16* __restrict__ oH, bf16* __restrict__ oL) {
    int warp = (blockIdx.x * blockDim.x + threadIdx.x) >> 5;
    int lane = threadIdx.x & 31;
    if (warp >= GN) return;
    const float* e = enc + (size_t)warp * EDIM;
    float v[8];
    float s = 0.f;
#pragma unroll
    for (int i = 0; i < 8; i++) { v[i] = e[lane + i * 32]; s += v[i]; }
#pragma unroll
    for (int o = 16; o; o >>= 1) s += __shfl_xor_sync(0xffffffffu, s, o);
    float mean = s * (1.f / 256.f);
    float q = 0.f;
#pragma unroll
    for (int i = 0; i < 8; i++) { float d = v[i] - mean; q += d * d; }
#pragma unroll
    for (int o = 16; o; o >>= 1) q += __shfl_xor_sync(0xffffffffu, q, o);
    float inv = rsqrtf(q * (1.f / 256.f) + 1e-7f);
#pragma unroll
    for (int i = 0; i < 8; i++) {
        int c = lane + i * 32;
        size_t o = (size_t)warp * EDIM + c;
        split2((v[i] - mean) * inv * gamma[c] + beta[c], &oH[o], &oL[o]);
    }
}

// ---------------- host ----------------
static float* symaddr(const void* sym) {
    void* p = nullptr;
    cudaGetSymbolAddress(&p, sym);
    return (float*)p;
}
static bf16* symaddrb(const void* sym) {
    void* p = nullptr;
    cudaGetSymbolAddress(&p, sym);
    return (bf16*)p;
}

extern "C" void kernel_launch(void* const* d_in, const int* in_sizes, int n_in,
                              void* d_out, int out_size) {
    const float* x     = (const float*)d_in[0];
    const float* st1   = (const float*)d_in[1];
    const float* st2   = (const float*)d_in[2];
    const float* wih1  = (const float*)d_in[3];
    const float* whh1  = (const float*)d_in[4];
    const float* bih1  = (const float*)d_in[5];
    const float* bhh1  = (const float*)d_in[6];
    const float* wih2  = (const float*)d_in[7];
    const float* whh2  = (const float*)d_in[8];
    const float* bih2  = (const float*)d_in[9];
    const float* bhh2  = (const float*)d_in[10];
    const float* dw1   = (const float*)d_in[11];
    const float* db1   = (const float*)d_in[12];
    const float* enc_w = (const float*)d_in[13];
    const float* gam   = (const float*)d_in[14];
    const float* bet   = (const float*)d_in[15];
    const float* w2ih1 = (const float*)d_in[16];
    const float* w2hh1 = (const float*)d_in[17];
    const float* b2ih1 = (const float*)d_in[18];
    const float* b2hh1 = (const float*)d_in[19];
    const float* w2ih2 = (const float*)d_in[20];
    const float* w2hh2 = (const float*)d_in[21];
    const float* b2ih2 = (const float*)d_in[22];
    const float* b2hh2 = (const float*)d_in[23];
    const float* dw2   = (const float*)d_in[24];
    const float* db2   = (const float*)d_in[25];
    const float* dec_w = (const float*)d_in[26];

    float* pmag  = symaddr(d_mag);
    float* pcos  = symaddr(d_cosF);
    float* psin  = symaddr(d_sinF);
    float* pm1   = symaddr(d_mask1);
    float* penc  = symaddr(d_enc);
    float* psA   = symaddr(d_sscrA);
    float* psB   = symaddr(d_sscrB);

    bf16* magH = symaddrb(d_magH);  bf16* magL = symaddrb(d_magL);
    bf16* y1H  = symaddrb(d_y1H);   bf16* y1L  = symaddrb(d_y1L);
    bf16* enH  = symaddrb(d_encnH); bf16* enL  = symaddrb(d_encnL);
    bf16* muH  = symaddrb(d_mulH);  bf16* muL  = symaddrb(d_mulL);
    bf16* h1aH = symaddrb(d_h1aH);  bf16* h1aL = symaddrb(d_h1aL);
    bf16* h2aH = symaddrb(d_h2aH);  bf16* h2aL = symaddrb(d_h2aL);
    bf16* h1bH = symaddrb(d_h1bH);  bf16* h1bL = symaddrb(d_h1bL);
    bf16* h2bH = symaddrb(d_h2bH);  bf16* h2bL = symaddrb(d_h2bL);
    bf16* hnAH = symaddrb(d_hnAH);  bf16* hnAL = symaddrb(d_hnAL);
    bf16* hnBH = symaddrb(d_hnBH);  bf16* hnBL = symaddrb(d_hnBL);
    bf16* wpH  = symaddrb(d_wpH);   bf16* wpL  = symaddrb(d_wpL);

    cudaFuncSetAttribute((const void*)mma_gemm<0>, cudaFuncAttributeMaxDynamicSharedMemorySize, SMEM_BYTES);
    cudaFuncSetAttribute((const void*)mma_gemm<1>, cudaFuncAttributeMaxDynamicSharedMemorySize, SMEM_BYTES);
    cudaFuncSetAttribute((const void*)mma_gemm<2>, cudaFuncAttributeMaxDynamicSharedMemorySize, SMEM_BYTES);
    cudaFuncSetAttribute((const void*)mma_gemm<3>, cudaFuncAttributeMaxDynamicSharedMemorySize, SMEM_BYTES);

    float* out = (float*)d_out;
    bool full = (out_size >= 3 * GN * 512);
    float* out_dec = out;
    float* out_s1 = full ? out + (size_t)GN * 512 : psA;
    float* out_s2 = full ? out + (size_t)2 * GN * 512 : psB;

    const int PT = GN * HID / 256;

    init_tw<<<1, 256>>>();

    // fused weight conversion (one launch); LSTM weights gate-interleaved
    {
        WConvArgs a;
        const float* s[12] = {wih1, whh1, wih2, whh2, dw1, enc_w, w2ih1, w2hh1, w2ih2, w2hh2, dw2, dec_w};
        int Ms[12]  = {512, 512, 512, 512, 257, 256, 512, 512, 512, 512, 256, 512};
        int Ks[12]  = {FB,  128, 128, 128, 128, 512, 256, 128, 128, 128, 128, 256};
        int Kp[12]  = {320, 128, 128, 128, 128, 512, 256, 128, 128, 128, 128, 256};
        int off[12] = {WP_W1A, WP_W1B, WP_W2A, WP_W2B, WP_DW1, WP_ENC,
                       WP_S1A, WP_S1B, WP_S2A, WP_S2B, WP_DW2, WP_DEC};
        int il[12]  = {1, 1, 1, 1, 0, 0, 1, 1, 1, 1, 0, 0};
        for (int i = 0; i < 12; i++) {
            a.src[i] = s[i]; a.M[i] = Ms[i]; a.K[i] = Ks[i];
            a.Kpad[i] = Kp[i]; a.off[i] = off[i]; a.ilv[i] = il[i];
        }
        convW_all<<<(WP_TOT + 255) / 256, 256>>>(a);
    }

    fft_fwd<<<GN, 256>>>(x, pmag, pcos, psin, magH, magL);
    extract_h<<<PT, 256>>>(st1, st2);

    // ---- sep block 1: two fused gates-GEMM+LSTM, then mask GEMM ----
    mma_gemm<3><<<dim3(4, 128), 256, SMEM_BYTES>>>(
        magH, magL, 320, h1aH, h1aL, 128,
        wpH + WP_W1A, wpL + WP_W1A, wpH + WP_W1B, wpL + WP_W1B,
        bih1, bhh1, out_s1, 512, st1, hnAH, hnAL);
    mma_gemm<3><<<dim3(4, 128), 256, SMEM_BYTES>>>(
        hnAH, hnAL, 128, h2aH, h2aL, 128,
        wpH + WP_W2A, wpL + WP_W2A, wpH + WP_W2B, wpL + WP_W2B,
        bih2, bhh2, out_s1 + (size_t)GN * 256, 512, st1 + (size_t)GN * 256, hnBH, hnBL);
    mma_gemm<1><<<dim3(3, 128), 256, SMEM_BYTES>>>(
        hnBH, hnBL, 128, nullptr, nullptr, 0,
        wpH + WP_DW1, wpL + WP_DW1, nullptr, nullptr,
        db1, nullptr, pm1, FB, nullptr, nullptr, nullptr);

    // ---- istft + encoder + layernorm ----
    ifft_apply<<<GN, 256>>>(pm1, pmag, pcos, psin, y1H, y1L);
    mma_gemm<0><<<dim3(2, 128), 256, SMEM_BYTES>>>(
        y1H, y1L, 512, nullptr, nullptr, 0,
        wpH + WP_ENC, wpL + WP_ENC, nullptr, nullptr,
        nullptr, nullptr, penc, EDIM, nullptr, nullptr, nullptr);
    ln_kernel<<<GN / 8, 256>>>(penc, gam, bet, enH, enL);

    // ---- sep block 2 ----
    mma_gemm<3><<<dim3(4, 128), 256, SMEM_BYTES>>>(
        enH, enL, 256, h1bH, h1bL, 128,
        wpH + WP_S1A, wpL + WP_S1A, wpH + WP_S1B, wpL + WP_S1B,
        b2ih1, b2hh1, out_s2, 512, st2, hnAH, hnAL);
    mma_gemm<3><<<dim3(4, 128), 256, SMEM_BYTES>>>(
        hnAH, hnAL, 128, h2bH, h2bL, 128,
        wpH + WP_S2A, wpL + WP_S2A, wpH + WP_S2B, wpL + WP_S2B,
        b2ih2, b2hh2, out_s2 + (size_t)GN * 256, 512, st2 + (size_t)GN * 256, hnBH, hnBL);
    // mask2 GEMM fused with (mask2 * enc) -> bf16 split
    mma_gemm<2><<<dim3(2, 128), 256, SMEM_BYTES>>>(
        hnBH, hnBL, 128, nullptr, nullptr, 0,
        wpH + WP_DW2, wpL + WP_DW2, nullptr, nullptr,
        db2, nullptr, nullptr, EDIM, penc, muH, muL);

    // ---- decode ----
    mma_gemm<0><<<dim3(4, 128), 256, SMEM_BYTES>>>(
        muH, muL, 256, nullptr, nullptr, 0,
        wpH + WP_DEC, wpL + WP_DEC, nullptr, nullptr,
        nullptr, nullptr, out_dec, FDIM, nullptr, nullptr, nullptr);
}

// round 15
// speedup vs baseline: 1.1295x; 1.1295x over previous
#include <cuda_runtime.h>
#include <cuda_bf16.h>
#include <math.h>
#include <stdint.h>

#define GN 16384
#define HID 128
#define FB 257
#define FDIM 512
#define EDIM 256
#define FEPS 1.1920929e-07f

typedef __nv_bfloat16 bf16;

// ---------------- scratch (__device__ globals) ----------------
static __device__ float d_twr[256], d_twi[256];
static __device__ float d_mag[GN * FB], d_cosF[GN * FB], d_sinF[GN * FB];
static __device__ float d_G[(size_t)GN * 512];
static __device__ float d_mask1[GN * FB];
static __device__ float d_enc[(size_t)GN * EDIM];
static __device__ float d_sscrA[(size_t)GN * 512], d_sscrB[(size_t)GN * 512];

// bf16 hi/lo activation buffers
#define KMAG 320
static __device__ bf16 d_magH[(size_t)GN * KMAG], d_magL[(size_t)GN * KMAG];
static __device__ bf16 d_y1H[(size_t)GN * 512],  d_y1L[(size_t)GN * 512];
static __device__ bf16 d_encnH[(size_t)GN * 256], d_encnL[(size_t)GN * 256];
static __device__ bf16 d_mulH[(size_t)GN * 256],  d_mulL[(size_t)GN * 256];
static __device__ bf16 d_h1aH[GN * HID], d_h1aL[GN * HID];
static __device__ bf16 d_h2aH[GN * HID], d_h2aL[GN * HID];
static __device__ bf16 d_h1bH[GN * HID], d_h1bL[GN * HID];
static __device__ bf16 d_h2bH[GN * HID], d_h2bL[GN * HID];
static __device__ bf16 d_hnAH[GN * HID], d_hnAL[GN * HID];
static __device__ bf16 d_hnBH[GN * HID], d_hnBL[GN * HID];

// weight pool (padded bf16 hi/lo), element offsets
#define WP_W1A   0          // wih1   512x320
#define WP_W1B   163840     // whh1   512x128
#define WP_W2A   229376     // wih2   512x128
#define WP_W2B   294912     // whh2   512x128
#define WP_DW1   360448     // dw1    384x128
#define WP_ENC   409600     // enc_w  256x512
#define WP_S1A   540672     // s2_wih1 512x256
#define WP_S1B   671744     // s2_whh1 512x128
#define WP_S2A   737280     // s2_wih2 512x128
#define WP_S2B   802816     // s2_whh2 512x128
#define WP_DW2   868352     // s2_dw  256x128
#define WP_DEC   901120     // dec_w  512x256
#define WP_TOT   1032192
static __device__ bf16 d_wpH[WP_TOT], d_wpL[WP_TOT];

__device__ __forceinline__ float sigm(float x) { return 1.f / (1.f + __expf(-x)); }

__device__ __forceinline__ void split2(float v, bf16* ph, bf16* pl) {
    bf16 h = __float2bfloat16(v);
    *ph = h;
    *pl = __float2bfloat16(v - __bfloat162float(h));
}
// split 4 floats into packed hi/lo bf16x4 (uint2 each)
__device__ __forceinline__ void split4pack(const float* v, uint2* hi, uint2* lo) {
    bf16 h[4], l[4];
#pragma unroll
    for (int i = 0; i < 4; i++) {
        h[i] = __float2bfloat16(v[i]);
        l[i] = __float2bfloat16(v[i] - __bfloat162float(h[i]));
    }
    uint2 H, L;
    memcpy(&H, h, 8);
    memcpy(&L, l, 8);
    *hi = H;
    *lo = L;
}

// ---------------- PTX helpers ----------------
__device__ __forceinline__ void cp16(uint32_t dst, const void* src) {
    asm volatile("cp.async.cg.shared.global [%0], [%1], 16;" :: "r"(dst), "l"(src));
}
__device__ __forceinline__ void ldm4(uint32_t* r, uint32_t a) {
    asm volatile("ldmatrix.sync.aligned.m8n8.x4.shared.b16 {%0,%1,%2,%3}, [%4];"
                 : "=r"(r[0]), "=r"(r[1]), "=r"(r[2]), "=r"(r[3]) : "r"(a));
}
__device__ __forceinline__ void mma16816(float* c, const uint32_t* a, const uint32_t* b) {
    asm volatile(
        "mma.sync.aligned.m16n8k16.row.col.f32.bf16.bf16.f32 "
        "{%0,%1,%2,%3}, {%4,%5,%6,%7}, {%8,%9}, {%0,%1,%2,%3};"
        : "+f"(c[0]), "+f"(c[1]), "+f"(c[2]), "+f"(c[3])
        : "r"(a[0]), "r"(a[1]), "r"(a[2]), "r"(a[3]), "r"(b[0]), "r"(b[1]));
}

// ---------------- twiddles ----------------
__global__ void init_tw() {
    int k = threadIdx.x;
    float s, c;
    sincospif(-(float)k / 256.f, &s, &c);
    d_twr[k] = c;
    d_twi[k] = s;
}

// ---------------- forward rFFT (512) + mag/cos/sin ----------------
__global__ void fft_fwd(const float* __restrict__ x,
                        float* __restrict__ mag, float* __restrict__ cosF, float* __restrict__ sinF,
                        bf16* __restrict__ magH, bf16* __restrict__ magL) {
    __shared__ float re[512], im[512];
    int n = blockIdx.x;
    int t = threadIdx.x;
    const float* xr = x + (size_t)n * 512;
    // coalesced global read, bit-reversed smem scatter (brev is an involution)
    for (int i = t; i < 512; i += 256) {
        int p = __brev(i) >> 23;
        re[p] = xr[i];
        im[i] = 0.f;
    }
    __syncthreads();
#pragma unroll
    for (int s = 1; s <= 9; ++s) {
        int half = 1 << (s - 1);
        int grp = t >> (s - 1);
        int j = t & (half - 1);
        int idx = (grp << s) + j;
        int twidx = j << (9 - s);
        float wr = d_twr[twidx], wi = d_twi[twidx];
        float ur = re[idx], ui = im[idx];
        float vr = re[idx + half], vi = im[idx + half];
        float tr = vr * wr - vi * wi;
        float ti = vr * wi + vi * wr;
        re[idx] = ur + tr;
        im[idx] = ui + ti;
        re[idx + half] = ur - tr;
        im[idx + half] = ui - ti;
        __syncthreads();
    }
    for (int k = t; k < KMAG; k += 256) {
        size_t op = (size_t)n * KMAG + k;
        if (k < FB) {
            float r = re[k], i2 = im[k];
            float mg = sqrtf(fmaxf(r * r + i2 * i2, FEPS));
            float rp = r + FEPS, ip = i2 + FEPS;
            float h = sqrtf(rp * rp + ip * ip);
            float inv = (h > 0.f) ? (1.f / h) : 0.f;
            size_t o = (size_t)n * FB + k;
            mag[o] = mg;
            cosF[o] = (h > 0.f) ? rp * inv : 1.f;
            sinF[o] = ip * inv;
            split2(mg, &magH[op], &magL[op]);
        } else {
            magH[op] = __float2bfloat16(0.f);
            magL[op] = __float2bfloat16(0.f);
        }
    }
}

// ---------------- apply mask + inverse rFFT -> y1 (bf16 hi/lo) ----------------
__global__ void ifft_apply(const float* __restrict__ mask, const float* __restrict__ mag,
                           const float* __restrict__ cosF, const float* __restrict__ sinF,
                           bf16* __restrict__ yH, bf16* __restrict__ yL) {
    __shared__ float re[512], im[512];
    __shared__ float xr[FB], xi[FB];
    int n = blockIdx.x;
    int t = threadIdx.x;
    for (int k = t; k < FB; k += 256) {
        size_t o = (size_t)n * FB + k;
        float em = mask[o] * mag[o];
        xr[k] = em * cosF[o];
        xi[k] = em * sinF[o];
    }
    __syncthreads();
    for (int i = t; i < 512; i += 256) {
        int p = __brev(i) >> 23;
        if (p <= 256) { re[i] = xr[p]; im[i] = xi[p]; }
        else          { re[i] = xr[512 - p]; im[i] = -xi[512 - p]; }
    }
    __syncthreads();
#pragma unroll
    for (int s = 1; s <= 9; ++s) {
        int half = 1 << (s - 1);
        int grp = t >> (s - 1);
        int j = t & (half - 1);
        int idx = (grp << s) + j;
        int twidx = j << (9 - s);
        float wr = d_twr[twidx], wi = -d_twi[twidx];
        float ur = re[idx], ui = im[idx];
        float vr = re[idx + half], vi = im[idx + half];
        float tr = vr * wr - vi * wi;
        float ti = vr * wi + vi * wr;
        re[idx] = ur + tr;
        im[idx] = ui + ti;
        re[idx + half] = ur - tr;
        im[idx + half] = ui - ti;
        __syncthreads();
    }
    for (int i = t; i < 512; i += 256) {
        size_t o = (size_t)n * 512 + i;
        split2(re[i] * (1.f / 512.f), &yH[o], &yL[o]);
    }
}

// ---------------- fused weight conversion: all 12 weights in one launch ----------------
struct WConvArgs {
    const float* src[12];
    int M[12], K[12], Kpad[12], off[12];
};

__global__ void convW_all(WConvArgs a) {
    int idx = blockIdx.x * 256 + threadIdx.x;
    if (idx >= WP_TOT) return;
    int s = 0;
#pragma unroll
    for (int i = 1; i < 12; i++)
        if (idx >= a.off[i]) s = i;
    int local = idx - a.off[s];
    int Kp = a.Kpad[s];
    int row = local / Kp, k = local - row * Kp;
    float v = (row < a.M[s] && k < a.K[s]) ? a.src[s][(size_t)row * a.K[s] + k] : 0.f;
    split2(v, &d_wpH[idx], &d_wpL[idx]);
}

// ================= mma.sync bf16 split-precision GEMM =================
// C[GN,M] = A1@W1^T (+ A2@W2^T) + b1 (+ b2).
// MODE 0: linear -> C. MODE 1: sigmoid -> C. MODE 2: sigmoid * xtra -> (oH,oL) bf16 split.
// Tile 128x128, BK=64, 256 threads (8 warps 4m x 2n), 2-stage cp.async pipeline.
#define STG 65536u
#define SMEM_BYTES (2 * 65536)

__device__ __forceinline__ void load_stage(uint32_t sb,
                                           const bf16* __restrict__ Ah, const bf16* __restrict__ Al,
                                           const bf16* __restrict__ Wh, const bf16* __restrict__ Wl,
                                           int Kp, int k0, int row0, int col0, int tid) {
#pragma unroll
    for (int it = 0; it < 4; it++) {
        int idx = it * 256 + tid;
        int r = idx >> 3, c = idx & 7;
        uint32_t off = (uint32_t)(r * 128 + ((c ^ (r & 7)) * 16));
        size_t ga = (size_t)(row0 + r) * Kp + k0 + c * 8;
        size_t gw = (size_t)(col0 + r) * Kp + k0 + c * 8;
        cp16(sb + off,            Ah + ga);
        cp16(sb + 16384u + off,   Al + ga);
        cp16(sb + 32768u + off,   Wh + gw);
        cp16(sb + 49152u + off,   Wl + gw);
    }
}

template <int MODE>
__global__ void __launch_bounds__(256) mma_gemm(
    const bf16* __restrict__ aH, const bf16* __restrict__ aL, int K1p,
    const bf16* __restrict__ a2H, const bf16* __restrict__ a2L, int K2p,
    const bf16* __restrict__ w1H, const bf16* __restrict__ w1L,
    const bf16* __restrict__ w2H, const bf16* __restrict__ w2L,
    const float* __restrict__ b1, const float* __restrict__ b2,
    float* __restrict__ C, int M,
    const float* __restrict__ xtra, bf16* __restrict__ oH, bf16* __restrict__ oL) {
    extern __shared__ __align__(1024) char smem[];
    uint32_t sbase = (uint32_t)__cvta_generic_to_shared(smem);
    int tid = threadIdx.x;
    int lane = tid & 31, wid = tid >> 5;
    int wm = wid & 3, wn = wid >> 2;
    int row0 = blockIdx.y * 128, col0 = blockIdx.x * 128;

    float acc[2][8][4];
#pragma unroll
    for (int m = 0; m < 2; m++)
#pragma unroll
        for (int n = 0; n < 8; n++)
#pragma unroll
            for (int k = 0; k < 4; k++) acc[m][n][k] = 0.f;

    int NC1 = K1p >> 6;
    int NC2 = a2H ? (K2p >> 6) : 0;
    int NC = NC1 + NC2;

    auto seg = [&](int tt, const bf16*& Ah, const bf16*& Al, const bf16*& Wh, const bf16*& Wl,
                   int& Kp, int& k0) {
        if (tt < NC1) { Ah = aH;  Al = aL;  Wh = w1H; Wl = w1L; Kp = K1p; k0 = tt * 64; }
        else          { Ah = a2H; Al = a2L; Wh = w2H; Wl = w2L; Kp = K2p; k0 = (tt - NC1) * 64; }
    };

    // prologue: stage 0
    {
        const bf16 *Ah, *Al, *Wh, *Wl; int Kp, k0;
        seg(0, Ah, Al, Wh, Wl, Kp, k0);
        load_stage(sbase, Ah, Al, Wh, Wl, Kp, k0, row0, col0, tid);
        asm volatile("cp.async.commit_group;");
    }

    for (int ch = 0; ch < NC; ch++) {
        if (ch + 1 < NC) {
            const bf16 *Ah, *Al, *Wh, *Wl; int Kp, k0;
            seg(ch + 1, Ah, Al, Wh, Wl, Kp, k0);
            load_stage(sbase + (uint32_t)((ch + 1) & 1) * STG, Ah, Al, Wh, Wl, Kp, k0, row0, col0, tid);
            asm volatile("cp.async.commit_group;");
            asm volatile("cp.async.wait_group 1;");
        } else {
            asm volatile("cp.async.wait_group 0;");
        }
        __syncthreads();

        uint32_t sb = sbase + (uint32_t)(ch & 1) * STG;
#pragma unroll
        for (int s = 0; s < 4; s++) {
            uint32_t ah[2][4], al[2][4];
#pragma unroll
            for (int m = 0; m < 2; m++) {
                int row = wm * 32 + m * 16 + (lane & 15);
                int chunk = s * 2 + (lane >> 4);
                uint32_t off = (uint32_t)(row * 128 + ((chunk ^ (row & 7)) * 16));
                ldm4(ah[m], sb + off);
                ldm4(al[m], sb + 16384u + off);
            }
            uint32_t bh[4][4], bl[4][4];
#pragma unroll
            for (int p = 0; p < 4; p++) {
                int rw = wn * 64 + p * 16 + (lane & 7) + ((lane >> 4) & 1) * 8;
                int chunk = s * 2 + ((lane >> 3) & 1);
                uint32_t off = (uint32_t)(rw * 128 + ((chunk ^ (rw & 7)) * 16));
                ldm4(bh[p], sb + 32768u + off);
                ldm4(bl[p], sb + 49152u + off);
            }
#pragma unroll
            for (int m = 0; m < 2; m++)
#pragma unroll
                for (int p = 0; p < 4; p++)
#pragma unroll
                    for (int h = 0; h < 2; h++) {
                        float* cc = acc[m][p * 2 + h];
                        mma16816(cc, ah[m], &bh[p][h * 2]);
                        mma16816(cc, ah[m], &bl[p][h * 2]);
                        mma16816(cc, al[m], &bh[p][h * 2]);
                    }
        }
        __syncthreads();
    }

    // epilogue
#pragma unroll
    for (int m = 0; m < 2; m++) {
#pragma unroll
        for (int n = 0; n < 8; n++) {
            float* cc = acc[m][n];
            int r0 = row0 + wm * 32 + m * 16 + (lane >> 2);
            int c0 = col0 + wn * 64 + n * 8 + (lane & 3) * 2;
#pragma unroll
            for (int e = 0; e < 4; e++) {
                int row = r0 + (e >> 1) * 8;
                int col = c0 + (e & 1);
                if (col < M) {
                    float v = cc[e];
                    if (b1) v += __ldg(b1 + col);
                    if (b2) v += __ldg(b2 + col);
                    size_t oidx = (size_t)row * M + col;
                    if (MODE == 0) {
                        C[oidx] = v;
                    } else if (MODE == 1) {
                        C[oidx] = sigm(v);
                    } else {
                        float r = sigm(v) * __ldg(xtra + oidx);
                        split2(r, &oH[oidx], &oL[oidx]);
                    }
                }
            }
        }
    }
}

// ---------------- LSTM pointwise (vectorized: 4 hidden units / thread) ----------------
__global__ void lstm_point(const float* __restrict__ G, const float* __restrict__ st_pair,
                           bf16* __restrict__ hH, bf16* __restrict__ hL,
                           float* __restrict__ out_pair) {
    int idx = blockIdx.x * 256 + threadIdx.x;   // GN*32 groups
    int n = idx >> 5, q = idx & 31;             // j0 = 4q
    const float* g = G + (size_t)n * 512 + 4 * q;
    float4 gi = *reinterpret_cast<const float4*>(g);
    float4 gf = *reinterpret_cast<const float4*>(g + 128);
    float4 gg = *reinterpret_cast<const float4*>(g + 256);
    float4 go = *reinterpret_cast<const float4*>(g + 384);
    const float* sp = st_pair + (size_t)n * 256 + 8 * q;
    float4 s0 = *reinterpret_cast<const float4*>(sp);      // h0 c0 h1 c1
    float4 s1 = *reinterpret_cast<const float4*>(sp + 4);  // h2 c2 h3 c3
    float cp[4] = {s0.y, s0.w, s1.y, s1.w};
    float vi[4] = {gi.x, gi.y, gi.z, gi.w};
    float vf[4] = {gf.x, gf.y, gf.z, gf.w};
    float vg[4] = {gg.x, gg.y, gg.z, gg.w};
    float vo[4] = {go.x, go.y, go.z, go.w};
    float hn[4], cn[4];
#pragma unroll
    for (int e = 0; e < 4; e++) {
        cn[e] = sigm(vf[e]) * cp[e] + sigm(vi[e]) * tanhf(vg[e]);
        hn[e] = sigm(vo[e]) * tanhf(cn[e]);
    }
    float* op = out_pair + (size_t)n * 256 + 8 * q;
    *reinterpret_cast<float4*>(op)     = make_float4(hn[0], cn[0], hn[1], cn[1]);
    *reinterpret_cast<float4*>(op + 4) = make_float4(hn[2], cn[2], hn[3], cn[3]);
    uint2 H, L;
    split4pack(hn, &H, &L);
    *reinterpret_cast<uint2*>(hH + (size_t)n * 128 + 4 * q) = H;
    *reinterpret_cast<uint2*>(hL + (size_t)n * 128 + 4 * q) = L;
}

// ---------------- extract h from interleaved states -> bf16 hi/lo (vectorized) ----------------
__global__ void extract_h(const float* __restrict__ s1, const float* __restrict__ s2) {
    int idx = blockIdx.x * 256 + threadIdx.x;   // GN*32 groups
    int n = idx >> 5, q = idx & 31;
    size_t base0 = (size_t)n * 256 + 8 * q;
    size_t base1 = ((size_t)GN + n) * 256 + 8 * q;
    size_t ob = (size_t)n * 128 + 4 * q;
    uint2 H, L;
    float h[4];
    float4 a, b;

    a = *reinterpret_cast<const float4*>(s1 + base0);
    b = *reinterpret_cast<const float4*>(s1 + base0 + 4);
    h[0] = a.x; h[1] = a.z; h[2] = b.x; h[3] = b.z;
    split4pack(h, &H, &L);
    *reinterpret_cast<uint2*>(d_h1aH + ob) = H;
    *reinterpret_cast<uint2*>(d_h1aL + ob) = L;

    a = *reinterpret_cast<const float4*>(s1 + base1);
    b = *reinterpret_cast<const float4*>(s1 + base1 + 4);
    h[0] = a.x; h[1] = a.z; h[2] = b.x; h[3] = b.z;
    split4pack(h, &H, &L);
    *reinterpret_cast<uint2*>(d_h2aH + ob) = H;
    *reinterpret_cast<uint2*>(d_h2aL + ob) = L;

    a = *reinterpret_cast<const float4*>(s2 + base0);
    b = *reinterpret_cast<const float4*>(s2 + base0 + 4);
    h[0] = a.x; h[1] = a.z; h[2] = b.x; h[3] = b.z;
    split4pack(h, &H, &L);
    *reinterpret_cast<uint2*>(d_h1bH + ob) = H;
    *reinterpret_cast<uint2*>(d_h1bL + ob) = L;

    a = *reinterpret_cast<const float4*>(s2 + base1);
    b = *reinterpret_cast<const float4*>(s2 + base1 + 4);
    h[0] = a.x; h[1] = a.z; h[2] = b.x; h[3] = b.z;
    split4pack(h, &H, &L);
    *reinterpret_cast<uint2*>(d_h2bH + ob) = H;
    *reinterpret_cast<uint2*>(d_h2bL + ob) = L;
}

// ---------------- layernorm over 256 -> bf16 hi/lo ----------------
__global__ void ln_kernel(const float* __restrict__ enc, const float* __restrict__ gamma,
                          const float* __restrict__ beta,
                          bf16* __restrict__ oH, bf16* __restrict__ oL) {
    int warp = (blockIdx.x * blockDim.x + threadIdx.x) >> 5;
    int lane = threadIdx.x & 31;
    if (warp >= GN) return;
    const float* e = enc + (size_t)warp * EDIM;
    float v[8];
    float s = 0.f;
#pragma unroll
    for (int i = 0; i < 8; i++) { v[i] = e[lane + i * 32]; s += v[i]; }
#pragma unroll
    for (int o = 16; o; o >>= 1) s += __shfl_xor_sync(0xffffffffu, s, o);
    float mean = s * (1.f / 256.f);
    float q = 0.f;
#pragma unroll
    for (int i = 0; i < 8; i++) { float d = v[i] - mean; q += d * d; }
#pragma unroll
    for (int o = 16; o; o >>= 1) q += __shfl_xor_sync(0xffffffffu, q, o);
    float inv = rsqrtf(q * (1.f / 256.f) + 1e-7f);
#pragma unroll
    for (int i = 0; i < 8; i++) {
        int c = lane + i * 32;
        size_t o = (size_t)warp * EDIM + c;
        split2((v[i] - mean) * inv * gamma[c] + beta[c], &oH[o], &oL[o]);
    }
}

// ---------------- host ----------------
static float* symaddr(const void* sym) {
    void* p = nullptr;
    cudaGetSymbolAddress(&p, sym);
    return (float*)p;
}
static bf16* symaddrb(const void* sym) {
    void* p = nullptr;
    cudaGetSymbolAddress(&p, sym);
    return (bf16*)p;
}

extern "C" void kernel_launch(void* const* d_in, const int* in_sizes, int n_in,
                              void* d_out, int out_size) {
    const float* x     = (const float*)d_in[0];
    const float* st1   = (const float*)d_in[1];
    const float* st2   = (const float*)d_in[2];
    const float* wih1  = (const float*)d_in[3];
    const float* whh1  = (const float*)d_in[4];
    const float* bih1  = (const float*)d_in[5];
    const float* bhh1  = (const float*)d_in[6];
    const float* wih2  = (const float*)d_in[7];
    const float* whh2  = (const float*)d_in[8];
    const float* bih2  = (const float*)d_in[9];
    const float* bhh2  = (const float*)d_in[10];
    const float* dw1   = (const float*)d_in[11];
    const float* db1   = (const float*)d_in[12];
    const float* enc_w = (const float*)d_in[13];
    const float* gam   = (const float*)d_in[14];
    const float* bet   = (const float*)d_in[15];
    const float* w2ih1 = (const float*)d_in[16];
    const float* w2hh1 = (const float*)d_in[17];
    const float* b2ih1 = (const float*)d_in[18];
    const float* b2hh1 = (const float*)d_in[19];
    const float* w2ih2 = (const float*)d_in[20];
    const float* w2hh2 = (const float*)d_in[21];
    const float* b2ih2 = (const float*)d_in[22];
    const float* b2hh2 = (const float*)d_in[23];
    const float* dw2   = (const float*)d_in[24];
    const float* db2   = (const float*)d_in[25];
    const float* dec_w = (const float*)d_in[26];

    float* pmag  = symaddr(d_mag);
    float* pcos  = symaddr(d_cosF);
    float* psin  = symaddr(d_sinF);
    float* pG    = symaddr(d_G);
    float* pm1   = symaddr(d_mask1);
    float* penc  = symaddr(d_enc);
    float* psA   = symaddr(d_sscrA);
    float* psB   = symaddr(d_sscrB);

    bf16* magH = symaddrb(d_magH);  bf16* magL = symaddrb(d_magL);
    bf16* y1H  = symaddrb(d_y1H);   bf16* y1L  = symaddrb(d_y1L);
    bf16* enH  = symaddrb(d_encnH); bf16* enL  = symaddrb(d_encnL);
    bf16* muH  = symaddrb(d_mulH);  bf16* muL  = symaddrb(d_mulL);
    bf16* h1aH = symaddrb(d_h1aH);  bf16* h1aL = symaddrb(d_h1aL);
    bf16* h2aH = symaddrb(d_h2aH);  bf16* h2aL = symaddrb(d_h2aL);
    bf16* h1bH = symaddrb(d_h1bH);  bf16* h1bL = symaddrb(d_h1bL);
    bf16* h2bH = symaddrb(d_h2bH);  bf16* h2bL = symaddrb(d_h2bL);
    bf16* hnAH = symaddrb(d_hnAH);  bf16* hnAL = symaddrb(d_hnAL);
    bf16* hnBH = symaddrb(d_hnBH);  bf16* hnBL = symaddrb(d_hnBL);
    bf16* wpH  = symaddrb(d_wpH);   bf16* wpL  = symaddrb(d_wpL);

    cudaFuncSetAttribute((const void*)mma_gemm<0>, cudaFuncAttributeMaxDynamicSharedMemorySize, SMEM_BYTES);
    cudaFuncSetAttribute((const void*)mma_gemm<1>, cudaFuncAttributeMaxDynamicSharedMemorySize, SMEM_BYTES);
    cudaFuncSetAttribute((const void*)mma_gemm<2>, cudaFuncAttributeMaxDynamicSharedMemorySize, SMEM_BYTES);

    float* out = (float*)d_out;
    bool full = (out_size >= 3 * GN * 512);
    float* out_dec = out;
    float* out_s1 = full ? out + (size_t)GN * 512 : psA;
    float* out_s2 = full ? out + (size_t)2 * GN * 512 : psB;

    const int PTV = GN * 32 / 256;  // vectorized pointwise grid (2048)

    init_tw<<<1, 256>>>();

    // fused weight conversion (one launch)
    {
        WConvArgs a;
        const float* s[12] = {wih1, whh1, wih2, whh2, dw1, enc_w, w2ih1, w2hh1, w2ih2, w2hh2, dw2, dec_w};
        int Ms[12]  = {512, 512, 512, 512, 257, 256, 512, 512, 512, 512, 256, 512};
        int Ks[12]  = {FB,  128, 128, 128, 128, 512, 256, 128, 128, 128, 128, 256};
        int Kp[12]  = {320, 128, 128, 128, 128, 512, 256, 128, 128, 128, 128, 256};
        int off[12] = {WP_W1A, WP_W1B, WP_W2A, WP_W2B, WP_DW1, WP_ENC,
                       WP_S1A, WP_S1B, WP_S2A, WP_S2B, WP_DW2, WP_DEC};
        for (int i = 0; i < 12; i++) {
            a.src[i] = s[i]; a.M[i] = Ms[i]; a.K[i] = Ks[i];
            a.Kpad[i] = Kp[i]; a.off[i] = off[i];
        }
        convW_all<<<(WP_TOT + 255) / 256, 256>>>(a);
    }

    fft_fwd<<<GN, 256>>>(x, pmag, pcos, psin, magH, magL);
    extract_h<<<PTV, 256>>>(st1, st2);

    // ---- sep block 1 ----
    mma_gemm<0><<<dim3(4, 128), 256, SMEM_BYTES>>>(
        magH, magL, 320, h1aH, h1aL, 128,
        wpH + WP_W1A, wpL + WP_W1A, wpH + WP_W1B, wpL + WP_W1B,
        bih1, bhh1, pG, 512, nullptr, nullptr, nullptr);
    lstm_point<<<PTV, 256>>>(pG, st1, hnAH, hnAL, out_s1);
    mma_gemm<0><<<dim3(4, 128), 256, SMEM_BYTES>>>(
        hnAH, hnAL, 128, h2aH, h2aL, 128,
        wpH + WP_W2A, wpL + WP_W2A, wpH + WP_W2B, wpL + WP_W2B,
        bih2, bhh2, pG, 512, nullptr, nullptr, nullptr);
    lstm_point<<<PTV, 256>>>(pG, st1 + (size_t)GN * 256, hnBH, hnBL, out_s1 + (size_t)GN * 256);
    mma_gemm<1><<<dim3(3, 128), 256, SMEM_BYTES>>>(
        hnBH, hnBL, 128, nullptr, nullptr, 0,
        wpH + WP_DW1, wpL + WP_DW1, nullptr, nullptr,
        db1, nullptr, pm1, FB, nullptr, nullptr, nullptr);

    // ---- istft + encoder + layernorm ----
    ifft_apply<<<GN, 256>>>(pm1, pmag, pcos, psin, y1H, y1L);
    mma_gemm<0><<<dim3(2, 128), 256, SMEM_BYTES>>>(
        y1H, y1L, 512, nullptr, nullptr, 0,
        wpH + WP_ENC, wpL + WP_ENC, nullptr, nullptr,
        nullptr, nullptr, penc, EDIM, nullptr, nullptr, nullptr);
    ln_kernel<<<GN / 8, 256>>>(penc, gam, bet, enH, enL);

    // ---- sep block 2 ----
    mma_gemm<0><<<dim3(4, 128), 256, SMEM_BYTES>>>(
        enH, enL, 256, h1bH, h1bL, 128,
        wpH + WP_S1A, wpL + WP_S1A, wpH + WP_S1B, wpL + WP_S1B,
        b2ih1, b2hh1, pG, 512, nullptr, nullptr, nullptr);
    lstm_point<<<PTV, 256>>>(pG, st2, hnAH, hnAL, out_s2);
    mma_gemm<0><<<dim3(4, 128), 256, SMEM_BYTES>>>(
        hnAH, hnAL, 128, h2bH, h2bL, 128,
        wpH + WP_S2A, wpL + WP_S2A, wpH + WP_S2B, wpL + WP_S2B,
        b2ih2, b2hh2, pG, 512, nullptr, nullptr, nullptr);
    lstm_point<<<PTV, 256>>>(pG, st2 + (size_t)GN * 256, hnBH, hnBL, out_s2 + (size_t)GN * 256);
    // mask2 GEMM fused with (mask2 * enc) -> bf16 split
    mma_gemm<2><<<dim3(2, 128), 256, SMEM_BYTES>>>(
        hnBH, hnBL, 128, nullptr, nullptr, 0,
        wpH + WP_DW2, wpL + WP_DW2, nullptr, nullptr,
        db2, nullptr, nullptr, EDIM, penc, muH, muL);

    // ---- decode ----
    mma_gemm<0><<<dim3(4, 128), 256, SMEM_BYTES>>>(
        muH, muL, 256, nullptr, nullptr, 0,
        wpH + WP_DEC, wpL + WP_DEC, nullptr, nullptr,
        nullptr, nullptr, out_dec, FDIM, nullptr, nullptr, nullptr);
}

// round 16
// speedup vs baseline: 1.2542x; 1.1104x over previous
#include <cuda_runtime.h>
#include <cuda_bf16.h>
#include <math.h>
#include <stdint.h>

#define GN 16384
#define HID 128
#define FB 257
#define FDIM 512
#define EDIM 256
#define FEPS 1.1920929e-07f

typedef __nv_bfloat16 bf16;

// ---------------- scratch (__device__ globals) ----------------
static __device__ float d_twr[256], d_twi[256];
static __device__ float d_mag[GN * FB], d_cosF[GN * FB], d_sinF[GN * FB];
static __device__ float d_G[(size_t)GN * 512];
static __device__ float d_mask1[GN * FB];
static __device__ float d_enc[(size_t)GN * EDIM];
static __device__ float d_sscrA[(size_t)GN * 512], d_sscrB[(size_t)GN * 512];

// bf16 hi/lo activation buffers
#define KMAG 320
static __device__ bf16 d_magH[(size_t)GN * KMAG], d_magL[(size_t)GN * KMAG];
static __device__ bf16 d_y1H[(size_t)GN * 512],  d_y1L[(size_t)GN * 512];
static __device__ bf16 d_encnH[(size_t)GN * 256], d_encnL[(size_t)GN * 256];
static __device__ bf16 d_mulH[(size_t)GN * 256],  d_mulL[(size_t)GN * 256];
static __device__ bf16 d_h1aH[GN * HID], d_h1aL[GN * HID];
static __device__ bf16 d_h2aH[GN * HID], d_h2aL[GN * HID];
static __device__ bf16 d_h1bH[GN * HID], d_h1bL[GN * HID];
static __device__ bf16 d_h2bH[GN * HID], d_h2bL[GN * HID];
static __device__ bf16 d_hnAH[GN * HID], d_hnAL[GN * HID];
static __device__ bf16 d_hnBH[GN * HID], d_hnBL[GN * HID];

// weight pool (padded bf16 hi/lo), element offsets
#define WP_W1A   0          // wih1   512x320
#define WP_W1B   163840     // whh1   512x128
#define WP_W2A   229376     // wih2   512x128
#define WP_W2B   294912     // whh2   512x128
#define WP_DW1   360448     // dw1    384x128
#define WP_ENC   409600     // enc_w  256x512
#define WP_S1A   540672     // s2_wih1 512x256
#define WP_S1B   671744     // s2_whh1 512x128
#define WP_S2A   737280     // s2_wih2 512x128
#define WP_S2B   802816     // s2_whh2 512x128
#define WP_DW2   868352     // s2_dw  256x128
#define WP_DEC   901120     // dec_w  512x256
#define WP_TOT   1032192
static __device__ bf16 d_wpH[WP_TOT], d_wpL[WP_TOT];

__device__ __forceinline__ float sigm(float x) { return 1.f / (1.f + __expf(-x)); }

__device__ __forceinline__ void split2(float v, bf16* ph, bf16* pl) {
    bf16 h = __float2bfloat16(v);
    *ph = h;
    *pl = __float2bfloat16(v - __bfloat162float(h));
}
// split 4 floats into packed hi/lo bf16x4 (uint2 each)
__device__ __forceinline__ void split4pack(const float* v, uint2* hi, uint2* lo) {
    bf16 h[4], l[4];
#pragma unroll
    for (int i = 0; i < 4; i++) {
        h[i] = __float2bfloat16(v[i]);
        l[i] = __float2bfloat16(v[i] - __bfloat162float(h[i]));
    }
    uint2 H, L;
    memcpy(&H, h, 8);
    memcpy(&L, l, 8);
    *hi = H;
    *lo = L;
}

// ---------------- PTX helpers ----------------
__device__ __forceinline__ void cp16(uint32_t dst, const void* src) {
    asm volatile("cp.async.cg.shared.global [%0], [%1], 16;" :: "r"(dst), "l"(src));
}
__device__ __forceinline__ void ldm4(uint32_t* r, uint32_t a) {
    asm volatile("ldmatrix.sync.aligned.m8n8.x4.shared.b16 {%0,%1,%2,%3}, [%4];"
                 : "=r"(r[0]), "=r"(r[1]), "=r"(r[2]), "=r"(r[3]) : "r"(a));
}
__device__ __forceinline__ void mma16816(float* c, const uint32_t* a, const uint32_t* b) {
    asm volatile(
        "mma.sync.aligned.m16n8k16.row.col.f32.bf16.bf16.f32 "
        "{%0,%1,%2,%3}, {%4,%5,%6,%7}, {%8,%9}, {%0,%1,%2,%3};"
        : "+f"(c[0]), "+f"(c[1]), "+f"(c[2]), "+f"(c[3])
        : "r"(a[0]), "r"(a[1]), "r"(a[2]), "r"(a[3]), "r"(b[0]), "r"(b[1]));
}

// ---------------- twiddles ----------------
__global__ void init_tw() {
    int k = threadIdx.x;
    float s, c;
    sincospif(-(float)k / 256.f, &s, &c);
    d_twr[k] = c;
    d_twi[k] = s;
}

// ---------------- forward rFFT (512) + mag/cos/sin ----------------
__global__ void fft_fwd(const float* __restrict__ x,
                        float* __restrict__ mag, float* __restrict__ cosF, float* __restrict__ sinF,
                        bf16* __restrict__ magH, bf16* __restrict__ magL) {
    __shared__ float re[512], im[512];
    int n = blockIdx.x;
    int t = threadIdx.x;
    const float* xr = x + (size_t)n * 512;
    for (int i = t; i < 512; i += 256) {
        int p = __brev(i) >> 23;
        re[p] = xr[i];
        im[i] = 0.f;
    }
    __syncthreads();
#pragma unroll
    for (int s = 1; s <= 9; ++s) {
        int half = 1 << (s - 1);
        int grp = t >> (s - 1);
        int j = t & (half - 1);
        int idx = (grp << s) + j;
        int twidx = j << (9 - s);
        float wr = d_twr[twidx], wi = d_twi[twidx];
        float ur = re[idx], ui = im[idx];
        float vr = re[idx + half], vi = im[idx + half];
        float tr = vr * wr - vi * wi;
        float ti = vr * wi + vi * wr;
        re[idx] = ur + tr;
        im[idx] = ui + ti;
        re[idx + half] = ur - tr;
        im[idx + half] = ui - ti;
        __syncthreads();
    }
    for (int k = t; k < KMAG; k += 256) {
        size_t op = (size_t)n * KMAG + k;
        if (k < FB) {
            float r = re[k], i2 = im[k];
            float mg = sqrtf(fmaxf(r * r + i2 * i2, FEPS));
            float rp = r + FEPS, ip = i2 + FEPS;
            float h = sqrtf(rp * rp + ip * ip);
            float inv = (h > 0.f) ? (1.f / h) : 0.f;
            size_t o = (size_t)n * FB + k;
            mag[o] = mg;
            cosF[o] = (h > 0.f) ? rp * inv : 1.f;
            sinF[o] = ip * inv;
            split2(mg, &magH[op], &magL[op]);
        } else {
            magH[op] = __float2bfloat16(0.f);
            magL[op] = __float2bfloat16(0.f);
        }
    }
}

// ---------------- apply mask + inverse rFFT -> y1 (bf16 hi/lo) ----------------
__global__ void ifft_apply(const float* __restrict__ mask, const float* __restrict__ mag,
                           const float* __restrict__ cosF, const float* __restrict__ sinF,
                           bf16* __restrict__ yH, bf16* __restrict__ yL) {
    __shared__ float re[512], im[512];
    __shared__ float xr[FB], xi[FB];
    int n = blockIdx.x;
    int t = threadIdx.x;
    for (int k = t; k < FB; k += 256) {
        size_t o = (size_t)n * FB + k;
        float em = mask[o] * mag[o];
        xr[k] = em * cosF[o];
        xi[k] = em * sinF[o];
    }
    __syncthreads();
    for (int i = t; i < 512; i += 256) {
        int p = __brev(i) >> 23;
        if (p <= 256) { re[i] = xr[p]; im[i] = xi[p]; }
        else          { re[i] = xr[512 - p]; im[i] = -xi[512 - p]; }
    }
    __syncthreads();
#pragma unroll
    for (int s = 1; s <= 9; ++s) {
        int half = 1 << (s - 1);
        int grp = t >> (s - 1);
        int j = t & (half - 1);
        int idx = (grp << s) + j;
        int twidx = j << (9 - s);
        float wr = d_twr[twidx], wi = -d_twi[twidx];
        float ur = re[idx], ui = im[idx];
        float vr = re[idx + half], vi = im[idx + half];
        float tr = vr * wr - vi * wi;
        float ti = vr * wi + vi * wr;
        re[idx] = ur + tr;
        im[idx] = ui + ti;
        re[idx + half] = ur - tr;
        im[idx + half] = ui - ti;
        __syncthreads();
    }
    for (int i = t; i < 512; i += 256) {
        size_t o = (size_t)n * 512 + i;
        split2(re[i] * (1.f / 512.f), &yH[o], &yL[o]);
    }
}

// ---------------- fused weight conversion: all 12 weights in one launch ----------------
struct WConvArgs {
    const float* src[12];
    int M[12], K[12], Kpad[12], off[12];
};

__global__ void convW_all(WConvArgs a) {
    int idx = blockIdx.x * 256 + threadIdx.x;
    if (idx >= WP_TOT) return;
    int s = 0;
#pragma unroll
    for (int i = 1; i < 12; i++)
        if (idx >= a.off[i]) s = i;
    int local = idx - a.off[s];
    int Kp = a.Kpad[s];
    int row = local / Kp, k = local - row * Kp;
    float v = (row < a.M[s] && k < a.K[s]) ? a.src[s][(size_t)row * a.K[s] + k] : 0.f;
    split2(v, &d_wpH[idx], &d_wpL[idx]);
}

// ================= mma.sync bf16 split-precision GEMM =================
// C[GN,M] = A1@W1^T (+ A2@W2^T) + b1 (+ b2).
// MODE 0: linear -> C. MODE 1: sigmoid -> C. MODE 2: sigmoid * xtra -> (oH,oL) bf16 split.
// Tile 128x64, BK=64, 256 threads (8 warps 4m x 2n; warp tile 32x32),
// 2-stage cp.async pipeline, 2 CTAs/SM (96KB smem/CTA).
#define STG 49152u
#define SMEM_BYTES (2 * 49152)

__device__ __forceinline__ void load_stage(uint32_t sb,
                                           const bf16* __restrict__ Ah, const bf16* __restrict__ Al,
                                           const bf16* __restrict__ Wh, const bf16* __restrict__ Wl,
                                           int Kp, int k0, int row0, int col0, int tid) {
#pragma unroll
    for (int it = 0; it < 4; it++) {
        int idx = it * 256 + tid;
        int r = idx >> 3, c = idx & 7;
        uint32_t off = (uint32_t)(r * 128 + ((c ^ (r & 7)) * 16));
        size_t ga = (size_t)(row0 + r) * Kp + k0 + c * 8;
        cp16(sb + off,          Ah + ga);
        cp16(sb + 16384u + off, Al + ga);
    }
#pragma unroll
    for (int it = 0; it < 2; it++) {
        int idx = it * 256 + tid;
        int r = idx >> 3, c = idx & 7;
        uint32_t off = (uint32_t)(r * 128 + ((c ^ (r & 7)) * 16));
        size_t gw = (size_t)(col0 + r) * Kp + k0 + c * 8;
        cp16(sb + 32768u + off, Wh + gw);
        cp16(sb + 40960u + off, Wl + gw);
    }
}

template <int MODE>
__global__ void __launch_bounds__(256, 2) mma_gemm(
    const bf16* __restrict__ aH, const bf16* __restrict__ aL, int K1p,
    const bf16* __restrict__ a2H, const bf16* __restrict__ a2L, int K2p,
    const bf16* __restrict__ w1H, const bf16* __restrict__ w1L,
    const bf16* __restrict__ w2H, const bf16* __restrict__ w2L,
    const float* __restrict__ b1, const float* __restrict__ b2,
    float* __restrict__ C, int M,
    const float* __restrict__ xtra, bf16* __restrict__ oH, bf16* __restrict__ oL) {
    extern __shared__ __align__(1024) char smem[];
    uint32_t sbase = (uint32_t)__cvta_generic_to_shared(smem);
    int tid = threadIdx.x;
    int lane = tid & 31, wid = tid >> 5;
    int wm = wid & 3, wn = wid >> 2;
    int row0 = blockIdx.y * 128, col0 = blockIdx.x * 64;

    float acc[2][4][4];
#pragma unroll
    for (int m = 0; m < 2; m++)
#pragma unroll
        for (int n = 0; n < 4; n++)
#pragma unroll
            for (int k = 0; k < 4; k++) acc[m][n][k] = 0.f;

    int NC1 = K1p >> 6;
    int NC2 = a2H ? (K2p >> 6) : 0;
    int NC = NC1 + NC2;

    auto seg = [&](int tt, const bf16*& Ah, const bf16*& Al, const bf16*& Wh, const bf16*& Wl,
                   int& Kp, int& k0) {
        if (tt < NC1) { Ah = aH;  Al = aL;  Wh = w1H; Wl = w1L; Kp = K1p; k0 = tt * 64; }
        else          { Ah = a2H; Al = a2L; Wh = w2H; Wl = w2L; Kp = K2p; k0 = (tt - NC1) * 64; }
    };

    // prologue: stage 0
    {
        const bf16 *Ah, *Al, *Wh, *Wl; int Kp, k0;
        seg(0, Ah, Al, Wh, Wl, Kp, k0);
        load_stage(sbase, Ah, Al, Wh, Wl, Kp, k0, row0, col0, tid);
        asm volatile("cp.async.commit_group;");
    }

    for (int ch = 0; ch < NC; ch++) {
        if (ch + 1 < NC) {
            const bf16 *Ah, *Al, *Wh, *Wl; int Kp, k0;
            seg(ch + 1, Ah, Al, Wh, Wl, Kp, k0);
            load_stage(sbase + (uint32_t)((ch + 1) & 1) * STG, Ah, Al, Wh, Wl, Kp, k0, row0, col0, tid);
            asm volatile("cp.async.commit_group;");
            asm volatile("cp.async.wait_group 1;");
        } else {
            asm volatile("cp.async.wait_group 0;");
        }
        __syncthreads();

        uint32_t sb = sbase + (uint32_t)(ch & 1) * STG;
#pragma unroll
        for (int s = 0; s < 4; s++) {
            uint32_t ah[2][4], al[2][4];
#pragma unroll
            for (int m = 0; m < 2; m++) {
                int row = wm * 32 + m * 16 + (lane & 15);
                int chunk = s * 2 + (lane >> 4);
                uint32_t off = (uint32_t)(row * 128 + ((chunk ^ (row & 7)) * 16));
                ldm4(ah[m], sb + off);
                ldm4(al[m], sb + 16384u + off);
            }
            uint32_t bh[2][4], bl[2][4];
#pragma unroll
            for (int p = 0; p < 2; p++) {
                int rw = wn * 32 + p * 16 + (lane & 7) + ((lane >> 4) & 1) * 8;
                int chunk = s * 2 + ((lane >> 3) & 1);
                uint32_t off = (uint32_t)(rw * 128 + ((chunk ^ (rw & 7)) * 16));
                ldm4(bh[p], sb + 32768u + off);
                ldm4(bl[p], sb + 40960u + off);
            }
#pragma unroll
            for (int m = 0; m < 2; m++)
#pragma unroll
                for (int p = 0; p < 2; p++)
#pragma unroll
                    for (int h = 0; h < 2; h++) {
                        float* cc = acc[m][p * 2 + h];
                        mma16816(cc, ah[m], &bh[p][h * 2]);
                        mma16816(cc, ah[m], &bl[p][h * 2]);
                        mma16816(cc, al[m], &bh[p][h * 2]);
                    }
        }
        __syncthreads();
    }

    // epilogue
#pragma unroll
    for (int m = 0; m < 2; m++) {
#pragma unroll
        for (int n = 0; n < 4; n++) {
            float* cc = acc[m][n];
            int r0 = row0 + wm * 32 + m * 16 + (lane >> 2);
            int c0 = col0 + wn * 32 + n * 8 + (lane & 3) * 2;
#pragma unroll
            for (int e = 0; e < 4; e++) {
                int row = r0 + (e >> 1) * 8;
                int col = c0 + (e & 1);
                if (col < M) {
                    float v = cc[e];
                    if (b1) v += __ldg(b1 + col);
                    if (b2) v += __ldg(b2 + col);
                    size_t oidx = (size_t)row * M + col;
                    if (MODE == 0) {
                        C[oidx] = v;
                    } else if (MODE == 1) {
                        C[oidx] = sigm(v);
                    } else {
                        float r = sigm(v) * __ldg(xtra + oidx);
                        split2(r, &oH[oidx], &oL[oidx]);
                    }
                }
            }
        }
    }
}

// ---------------- LSTM pointwise (vectorized: 4 hidden units / thread) ----------------
__global__ void lstm_point(const float* __restrict__ G, const float* __restrict__ st_pair,
                           bf16* __restrict__ hH, bf16* __restrict__ hL,
                           float* __restrict__ out_pair) {
    int idx = blockIdx.x * 256 + threadIdx.x;   // GN*32 groups
    int n = idx >> 5, q = idx & 31;             // j0 = 4q
    const float* g = G + (size_t)n * 512 + 4 * q;
    float4 gi = *reinterpret_cast<const float4*>(g);
    float4 gf = *reinterpret_cast<const float4*>(g + 128);
    float4 gg = *reinterpret_cast<const float4*>(g + 256);
    float4 go = *reinterpret_cast<const float4*>(g + 384);
    const float* sp = st_pair + (size_t)n * 256 + 8 * q;
    float4 s0 = *reinterpret_cast<const float4*>(sp);
    float4 s1 = *reinterpret_cast<const float4*>(sp + 4);
    float cp[4] = {s0.y, s0.w, s1.y, s1.w};
    float vi[4] = {gi.x, gi.y, gi.z, gi.w};
    float vf[4] = {gf.x, gf.y, gf.z, gf.w};
    float vg[4] = {gg.x, gg.y, gg.z, gg.w};
    float vo[4] = {go.x, go.y, go.z, go.w};
    float hn[4], cn[4];
#pragma unroll
    for (int e = 0; e < 4; e++) {
        cn[e] = sigm(vf[e]) * cp[e] + sigm(vi[e]) * tanhf(vg[e]);
        hn[e] = sigm(vo[e]) * tanhf(cn[e]);
    }
    float* op = out_pair + (size_t)n * 256 + 8 * q;
    *reinterpret_cast<float4*>(op)     = make_float4(hn[0], cn[0], hn[1], cn[1]);
    *reinterpret_cast<float4*>(op + 4) = make_float4(hn[2], cn[2], hn[3], cn[3]);
    uint2 H, L;
    split4pack(hn, &H, &L);
    *reinterpret_cast<uint2*>(hH + (size_t)n * 128 + 4 * q) = H;
    *reinterpret_cast<uint2*>(hL + (size_t)n * 128 + 4 * q) = L;
}

// ---------------- extract h from interleaved states -> bf16 hi/lo (vectorized) ----------------
__global__ void extract_h(const float* __restrict__ s1, const float* __restrict__ s2) {
    int idx = blockIdx.x * 256 + threadIdx.x;   // GN*32 groups
    int n = idx >> 5, q = idx & 31;
    size_t base0 = (size_t)n * 256 + 8 * q;
    size_t base1 = ((size_t)GN + n) * 256 + 8 * q;
    size_t ob = (size_t)n * 128 + 4 * q;
    uint2 H, L;
    float h[4];
    float4 a, b;

    a = *reinterpret_cast<const float4*>(s1 + base0);
    b = *reinterpret_cast<const float4*>(s1 + base0 + 4);
    h[0] = a.x; h[1] = a.z; h[2] = b.x; h[3] = b.z;
    split4pack(h, &H, &L);
    *reinterpret_cast<uint2*>(d_h1aH + ob) = H;
    *reinterpret_cast<uint2*>(d_h1aL + ob) = L;

    a = *reinterpret_cast<const float4*>(s1 + base1);
    b = *reinterpret_cast<const float4*>(s1 + base1 + 4);
    h[0] = a.x; h[1] = a.z; h[2] = b.x; h[3] = b.z;
    split4pack(h, &H, &L);
    *reinterpret_cast<uint2*>(d_h2aH + ob) = H;
    *reinterpret_cast<uint2*>(d_h2aL + ob) = L;

    a = *reinterpret_cast<const float4*>(s2 + base0);
    b = *reinterpret_cast<const float4*>(s2 + base0 + 4);
    h[0] = a.x; h[1] = a.z; h[2] = b.x; h[3] = b.z;
    split4pack(h, &H, &L);
    *reinterpret_cast<uint2*>(d_h1bH + ob) = H;
    *reinterpret_cast<uint2*>(d_h1bL + ob) = L;

    a = *reinterpret_cast<const float4*>(s2 + base1);
    b = *reinterpret_cast<const float4*>(s2 + base1 + 4);
    h[0] = a.x; h[1] = a.z; h[2] = b.x; h[3] = b.z;
    split4pack(h, &H, &L);
    *reinterpret_cast<uint2*>(d_h2bH + ob) = H;
    *reinterpret_cast<uint2*>(d_h2bL + ob) = L;
}

// ---------------- layernorm over 256 -> bf16 hi/lo ----------------
__global__ void ln_kernel(const float* __restrict__ enc, const float* __restrict__ gamma,
                          const float* __restrict__ beta,
                          bf16* __restrict__ oH, bf16* __restrict__ oL) {
    int warp = (blockIdx.x * blockDim.x + threadIdx.x) >> 5;
    int lane = threadIdx.x & 31;
    if (warp >= GN) return;
    const float* e = enc + (size_t)warp * EDIM;
    float v[8];
    float s = 0.f;
#pragma unroll
    for (int i = 0; i < 8; i++) { v[i] = e[lane + i * 32]; s += v[i]; }
#pragma unroll
    for (int o = 16; o; o >>= 1) s += __shfl_xor_sync(0xffffffffu, s, o);
    float mean = s * (1.f / 256.f);
    float q = 0.f;
#pragma unroll
    for (int i = 0; i < 8; i++) { float d = v[i] - mean; q += d * d; }
#pragma unroll
    for (int o = 16; o; o >>= 1) q += __shfl_xor_sync(0xffffffffu, q, o);
    float inv = rsqrtf(q * (1.f / 256.f) + 1e-7f);
#pragma unroll
    for (int i = 0; i < 8; i++) {
        int c = lane + i * 32;
        size_t o = (size_t)warp * EDIM + c;
        split2((v[i] - mean) * inv * gamma[c] + beta[c], &oH[o], &oL[o]);
    }
}

// ---------------- host ----------------
static float* symaddr(const void* sym) {
    void* p = nullptr;
    cudaGetSymbolAddress(&p, sym);
    return (float*)p;
}
static bf16* symaddrb(const void* sym) {
    void* p = nullptr;
    cudaGetSymbolAddress(&p, sym);
    return (bf16*)p;
}

extern "C" void kernel_launch(void* const* d_in, const int* in_sizes, int n_in,
                              void* d_out, int out_size) {
    const float* x     = (const float*)d_in[0];
    const float* st1   = (const float*)d_in[1];
    const float* st2   = (const float*)d_in[2];
    const float* wih1  = (const float*)d_in[3];
    const float* whh1  = (const float*)d_in[4];
    const float* bih1  = (const float*)d_in[5];
    const float* bhh1  = (const float*)d_in[6];
    const float* wih2  = (const float*)d_in[7];
    const float* whh2  = (const float*)d_in[8];
    const float* bih2  = (const float*)d_in[9];
    const float* bhh2  = (const float*)d_in[10];
    const float* dw1   = (const float*)d_in[11];
    const float* db1   = (const float*)d_in[12];
    const float* enc_w = (const float*)d_in[13];
    const float* gam   = (const float*)d_in[14];
    const float* bet   = (const float*)d_in[15];
    const float* w2ih1 = (const float*)d_in[16];
    const float* w2hh1 = (const float*)d_in[17];
    const float* b2ih1 = (const float*)d_in[18];
    const float* b2hh1 = (const float*)d_in[19];
    const float* w2ih2 = (const float*)d_in[20];
    const float* w2hh2 = (const float*)d_in[21];
    const float* b2ih2 = (const float*)d_in[22];
    const float* b2hh2 = (const float*)d_in[23];
    const float* dw2   = (const float*)d_in[24];
    const float* db2   = (const float*)d_in[25];
    const float* dec_w = (const float*)d_in[26];

    float* pmag  = symaddr(d_mag);
    float* pcos  = symaddr(d_cosF);
    float* psin  = symaddr(d_sinF);
    float* pG    = symaddr(d_G);
    float* pm1   = symaddr(d_mask1);
    float* penc  = symaddr(d_enc);
    float* psA   = symaddr(d_sscrA);
    float* psB   = symaddr(d_sscrB);

    bf16* magH = symaddrb(d_magH);  bf16* magL = symaddrb(d_magL);
    bf16* y1H  = symaddrb(d_y1H);   bf16* y1L  = symaddrb(d_y1L);
    bf16* enH  = symaddrb(d_encnH); bf16* enL  = symaddrb(d_encnL);
    bf16* muH  = symaddrb(d_mulH);  bf16* muL  = symaddrb(d_mulL);
    bf16* h1aH = symaddrb(d_h1aH);  bf16* h1aL = symaddrb(d_h1aL);
    bf16* h2aH = symaddrb(d_h2aH);  bf16* h2aL = symaddrb(d_h2aL);
    bf16* h1bH = symaddrb(d_h1bH);  bf16* h1bL = symaddrb(d_h1bL);
    bf16* h2bH = symaddrb(d_h2bH);  bf16* h2bL = symaddrb(d_h2bL);
    bf16* hnAH = symaddrb(d_hnAH);  bf16* hnAL = symaddrb(d_hnAL);
    bf16* hnBH = symaddrb(d_hnBH);  bf16* hnBL = symaddrb(d_hnBL);
    bf16* wpH  = symaddrb(d_wpH);   bf16* wpL  = symaddrb(d_wpL);

    cudaFuncSetAttribute((const void*)mma_gemm<0>, cudaFuncAttributeMaxDynamicSharedMemorySize, SMEM_BYTES);
    cudaFuncSetAttribute((const void*)mma_gemm<1>, cudaFuncAttributeMaxDynamicSharedMemorySize, SMEM_BYTES);
    cudaFuncSetAttribute((const void*)mma_gemm<2>, cudaFuncAttributeMaxDynamicSharedMemorySize, SMEM_BYTES);

    float* out = (float*)d_out;
    bool full = (out_size >= 3 * GN * 512);
    float* out_dec = out;
    float* out_s1 = full ? out + (size_t)GN * 512 : psA;
    float* out_s2 = full ? out + (size_t)2 * GN * 512 : psB;

    const int PTV = GN * 32 / 256;  // vectorized pointwise grid (2048)

    init_tw<<<1, 256>>>();

    // fused weight conversion (one launch)
    {
        WConvArgs a;
        const float* s[12] = {wih1, whh1, wih2, whh2, dw1, enc_w, w2ih1, w2hh1, w2ih2, w2hh2, dw2, dec_w};
        int Ms[12]  = {512, 512, 512, 512, 257, 256, 512, 512, 512, 512, 256, 512};
        int Ks[12]  = {FB,  128, 128, 128, 128, 512, 256, 128, 128, 128, 128, 256};
        int Kp[12]  = {320, 128, 128, 128, 128, 512, 256, 128, 128, 128, 128, 256};
        int off[12] = {WP_W1A, WP_W1B, WP_W2A, WP_W2B, WP_DW1, WP_ENC,
                       WP_S1A, WP_S1B, WP_S2A, WP_S2B, WP_DW2, WP_DEC};
        for (int i = 0; i < 12; i++) {
            a.src[i] = s[i]; a.M[i] = Ms[i]; a.K[i] = Ks[i];
            a.Kpad[i] = Kp[i]; a.off[i] = off[i];
        }
        convW_all<<<(WP_TOT + 255) / 256, 256>>>(a);
    }

    fft_fwd<<<GN, 256>>>(x, pmag, pcos, psin, magH, magL);
    extract_h<<<PTV, 256>>>(st1, st2);

    // ---- sep block 1 ----
    mma_gemm<0><<<dim3(8, 128), 256, SMEM_BYTES>>>(
        magH, magL, 320, h1aH, h1aL, 128,
        wpH + WP_W1A, wpL + WP_W1A, wpH + WP_W1B, wpL + WP_W1B,
        bih1, bhh1, pG, 512, nullptr, nullptr, nullptr);
    lstm_point<<<PTV, 256>>>(pG, st1, hnAH, hnAL, out_s1);
    mma_gemm<0><<<dim3(8, 128), 256, SMEM_BYTES>>>(
        hnAH, hnAL, 128, h2aH, h2aL, 128,
        wpH + WP_W2A, wpL + WP_W2A, wpH + WP_W2B, wpL + WP_W2B,
        bih2, bhh2, pG, 512, nullptr, nullptr, nullptr);
    lstm_point<<<PTV, 256>>>(pG, st1 + (size_t)GN * 256, hnBH, hnBL, out_s1 + (size_t)GN * 256);
    mma_gemm<1><<<dim3(5, 128), 256, SMEM_BYTES>>>(
        hnBH, hnBL, 128, nullptr, nullptr, 0,
        wpH + WP_DW1, wpL + WP_DW1, nullptr, nullptr,
        db1, nullptr, pm1, FB, nullptr, nullptr, nullptr);

    // ---- istft + encoder + layernorm ----
    ifft_apply<<<GN, 256>>>(pm1, pmag, pcos, psin, y1H, y1L);
    mma_gemm<0><<<dim3(4, 128), 256, SMEM_BYTES>>>(
        y1H, y1L, 512, nullptr, nullptr, 0,
        wpH + WP_ENC, wpL + WP_ENC, nullptr, nullptr,
        nullptr, nullptr, penc, EDIM, nullptr, nullptr, nullptr);
    ln_kernel<<<GN / 8, 256>>>(penc, gam, bet, enH, enL);

    // ---- sep block 2 ----
    mma_gemm<0><<<dim3(8, 128), 256, SMEM_BYTES>>>(
        enH, enL, 256, h1bH, h1bL, 128,
        wpH + WP_S1A, wpL + WP_S1A, wpH + WP_S1B, wpL + WP_S1B,
        b2ih1, b2hh1, pG, 512, nullptr, nullptr, nullptr);
    lstm_point<<<PTV, 256>>>(pG, st2, hnAH, hnAL, out_s2);
    mma_gemm<0><<<dim3(8, 128), 256, SMEM_BYTES>>>(
        hnAH, hnAL, 128, h2bH, h2bL, 128,
        wpH + WP_S2A, wpL + WP_S2A, wpH + WP_S2B, wpL + WP_S2B,
        b2ih2, b2hh2, pG, 512, nullptr, nullptr, nullptr);
    lstm_point<<<PTV, 256>>>(pG, st2 + (size_t)GN * 256, hnBH, hnBL, out_s2 + (size_t)GN * 256);
    // mask2 GEMM fused with (mask2 * enc) -> bf16 split
    mma_gemm<2><<<dim3(4, 128), 256, SMEM_BYTES>>>(
        hnBH, hnBL, 128, nullptr, nullptr, 0,
        wpH + WP_DW2, wpL + WP_DW2, nullptr, nullptr,
        db2, nullptr, nullptr, EDIM, penc, muH, muL);

    // ---- decode ----
    mma_gemm<0><<<dim3(8, 128), 256, SMEM_BYTES>>>(
        muH, muL, 256, nullptr, nullptr, 0,
        wpH + WP_DEC, wpL + WP_DEC, nullptr, nullptr,
        nullptr, nullptr, out_dec, FDIM, nullptr, nullptr, nullptr);
}

// round 17
// speedup vs baseline: 1.3626x; 1.0865x over previous
#include <cuda_runtime.h>
#include <cuda_bf16.h>
#include <math.h>
#include <stdint.h>

#define GN 16384
#define HID 128
#define FB 257
#define FDIM 512
#define EDIM 256
#define FEPS 1.1920929e-07f

typedef __nv_bfloat16 bf16;

// ---------------- scratch (__device__ globals) ----------------
static __device__ float d_twr[256], d_twi[256];
static __device__ float d_mag[GN * FB], d_cosF[GN * FB], d_sinF[GN * FB];
static __device__ float d_G[(size_t)GN * 512];
static __device__ float d_mask1[GN * FB];
static __device__ float d_enc[(size_t)GN * EDIM];
static __device__ float d_sscrA[(size_t)GN * 512], d_sscrB[(size_t)GN * 512];

// bf16 hi/lo activation buffers
#define KMAG 320
static __device__ bf16 d_magH[(size_t)GN * KMAG], d_magL[(size_t)GN * KMAG];
static __device__ bf16 d_y1H[(size_t)GN * 512],  d_y1L[(size_t)GN * 512];
static __device__ bf16 d_encnH[(size_t)GN * 256], d_encnL[(size_t)GN * 256];
static __device__ bf16 d_mulH[(size_t)GN * 256],  d_mulL[(size_t)GN * 256];
static __device__ bf16 d_h1aH[GN * HID], d_h1aL[GN * HID];
static __device__ bf16 d_h2aH[GN * HID], d_h2aL[GN * HID];
static __device__ bf16 d_h1bH[GN * HID], d_h1bL[GN * HID];
static __device__ bf16 d_h2bH[GN * HID], d_h2bL[GN * HID];
static __device__ bf16 d_hnAH[GN * HID], d_hnAL[GN * HID];
static __device__ bf16 d_hnBH[GN * HID], d_hnBL[GN * HID];

// weight pool (padded bf16 hi/lo), element offsets
#define WP_W1A   0          // wih1   512x320
#define WP_W1B   163840     // whh1   512x128
#define WP_W2A   229376     // wih2   512x128
#define WP_W2B   294912     // whh2   512x128
#define WP_DW1   360448     // dw1    384x128
#define WP_ENC   409600     // enc_w  256x512
#define WP_S1A   540672     // s2_wih1 512x256
#define WP_S1B   671744     // s2_whh1 512x128
#define WP_S2A   737280     // s2_wih2 512x128
#define WP_S2B   802816     // s2_whh2 512x128
#define WP_DW2   868352     // s2_dw  256x128
#define WP_DEC   901120     // dec_w  512x256
#define WP_TOT   1032192
static __device__ bf16 d_wpH[WP_TOT], d_wpL[WP_TOT];

__device__ __forceinline__ float sigm(float x) { return 1.f / (1.f + __expf(-x)); }

__device__ __forceinline__ void split2(float v, bf16* ph, bf16* pl) {
    bf16 h = __float2bfloat16(v);
    *ph = h;
    *pl = __float2bfloat16(v - __bfloat162float(h));
}
// split 4 floats into packed hi/lo bf16x4 (uint2 each)
__device__ __forceinline__ void split4pack(const float* v, uint2* hi, uint2* lo) {
    bf16 h[4], l[4];
#pragma unroll
    for (int i = 0; i < 4; i++) {
        h[i] = __float2bfloat16(v[i]);
        l[i] = __float2bfloat16(v[i] - __bfloat162float(h[i]));
    }
    uint2 H, L;
    memcpy(&H, h, 8);
    memcpy(&L, l, 8);
    *hi = H;
    *lo = L;
}

// ---------------- PTX helpers ----------------
__device__ __forceinline__ void cp16(uint32_t dst, const void* src) {
    asm volatile("cp.async.cg.shared.global [%0], [%1], 16;" :: "r"(dst), "l"(src));
}
__device__ __forceinline__ void ldm4(uint32_t* r, uint32_t a) {
    asm volatile("ldmatrix.sync.aligned.m8n8.x4.shared.b16 {%0,%1,%2,%3}, [%4];"
                 : "=r"(r[0]), "=r"(r[1]), "=r"(r[2]), "=r"(r[3]) : "r"(a));
}
__device__ __forceinline__ void mma16816(float* c, const uint32_t* a, const uint32_t* b) {
    asm volatile(
        "mma.sync.aligned.m16n8k16.row.col.f32.bf16.bf16.f32 "
        "{%0,%1,%2,%3}, {%4,%5,%6,%7}, {%8,%9}, {%0,%1,%2,%3};"
        : "+f"(c[0]), "+f"(c[1]), "+f"(c[2]), "+f"(c[3])
        : "r"(a[0]), "r"(a[1]), "r"(a[2]), "r"(a[3]), "r"(b[0]), "r"(b[1]));
}

// ---------------- twiddles ----------------
__global__ void init_tw() {
    int k = threadIdx.x;
    float s, c;
    sincospif(-(float)k / 256.f, &s, &c);
    d_twr[k] = c;
    d_twi[k] = s;
}

// ---------------- forward rFFT (512) + mag/cos/sin ----------------
__global__ void fft_fwd(const float* __restrict__ x,
                        float* __restrict__ mag, float* __restrict__ cosF, float* __restrict__ sinF,
                        bf16* __restrict__ magH, bf16* __restrict__ magL) {
    __shared__ float re[512], im[512];
    int n = blockIdx.x;
    int t = threadIdx.x;
    const float* xr = x + (size_t)n * 512;
    for (int i = t; i < 512; i += 256) {
        int p = __brev(i) >> 23;
        re[p] = xr[i];
        im[i] = 0.f;
    }
    __syncthreads();
#pragma unroll
    for (int s = 1; s <= 9; ++s) {
        int half = 1 << (s - 1);
        int grp = t >> (s - 1);
        int j = t & (half - 1);
        int idx = (grp << s) + j;
        int twidx = j << (9 - s);
        float wr = d_twr[twidx], wi = d_twi[twidx];
        float ur = re[idx], ui = im[idx];
        float vr = re[idx + half], vi = im[idx + half];
        float tr = vr * wr - vi * wi;
        float ti = vr * wi + vi * wr;
        re[idx] = ur + tr;
        im[idx] = ui + ti;
        re[idx + half] = ur - tr;
        im[idx + half] = ui - ti;
        __syncthreads();
    }
    for (int k = t; k < KMAG; k += 256) {
        size_t op = (size_t)n * KMAG + k;
        if (k < FB) {
            float r = re[k], i2 = im[k];
            float mg = sqrtf(fmaxf(r * r + i2 * i2, FEPS));
            float rp = r + FEPS, ip = i2 + FEPS;
            float h = sqrtf(rp * rp + ip * ip);
            float inv = (h > 0.f) ? (1.f / h) : 0.f;
            size_t o = (size_t)n * FB + k;
            mag[o] = mg;
            cosF[o] = (h > 0.f) ? rp * inv : 1.f;
            sinF[o] = ip * inv;
            split2(mg, &magH[op], &magL[op]);
        } else {
            magH[op] = __float2bfloat16(0.f);
            magL[op] = __float2bfloat16(0.f);
        }
    }
}

// ---------------- apply mask + inverse rFFT -> y1 (bf16 hi/lo) ----------------
__global__ void ifft_apply(const float* __restrict__ mask, const float* __restrict__ mag,
                           const float* __restrict__ cosF, const float* __restrict__ sinF,
                           bf16* __restrict__ yH, bf16* __restrict__ yL) {
    __shared__ float re[512], im[512];
    __shared__ float xr[FB], xi[FB];
    int n = blockIdx.x;
    int t = threadIdx.x;
    for (int k = t; k < FB; k += 256) {
        size_t o = (size_t)n * FB + k;
        float em = mask[o] * mag[o];
        xr[k] = em * cosF[o];
        xi[k] = em * sinF[o];
    }
    __syncthreads();
    for (int i = t; i < 512; i += 256) {
        int p = __brev(i) >> 23;
        if (p <= 256) { re[i] = xr[p]; im[i] = xi[p]; }
        else          { re[i] = xr[512 - p]; im[i] = -xi[512 - p]; }
    }
    __syncthreads();
#pragma unroll
    for (int s = 1; s <= 9; ++s) {
        int half = 1 << (s - 1);
        int grp = t >> (s - 1);
        int j = t & (half - 1);
        int idx = (grp << s) + j;
        int twidx = j << (9 - s);
        float wr = d_twr[twidx], wi = -d_twi[twidx];
        float ur = re[idx], ui = im[idx];
        float vr = re[idx + half], vi = im[idx + half];
        float tr = vr * wr - vi * wi;
        float ti = vr * wi + vi * wr;
        re[idx] = ur + tr;
        im[idx] = ui + ti;
        re[idx + half] = ur - tr;
        im[idx + half] = ui - ti;
        __syncthreads();
    }
    for (int i = t; i < 512; i += 256) {
        size_t o = (size_t)n * 512 + i;
        split2(re[i] * (1.f / 512.f), &yH[o], &yL[o]);
    }
}

// ---------------- fused weight conversion: all 12 weights in one launch ----------------
struct WConvArgs {
    const float* src[12];
    int M[12], K[12], Kpad[12], off[12];
};

__global__ void convW_all(WConvArgs a) {
    int idx = blockIdx.x * 256 + threadIdx.x;
    if (idx >= WP_TOT) return;
    int s = 0;
#pragma unroll
    for (int i = 1; i < 12; i++)
        if (idx >= a.off[i]) s = i;
    int local = idx - a.off[s];
    int Kp = a.Kpad[s];
    int row = local / Kp, k = local - row * Kp;
    float v = (row < a.M[s] && k < a.K[s]) ? a.src[s][(size_t)row * a.K[s] + k] : 0.f;
    split2(v, &d_wpH[idx], &d_wpL[idx]);
}

// ================= mma.sync bf16 split-precision GEMM =================
// C[GN,M] = A1@W1^T (+ A2@W2^T) + b1 (+ b2).
// MODE 0: linear -> C. MODE 1: sigmoid -> C. MODE 2: sigmoid * xtra -> (oH,oL) bf16 split.
// Tile 64x64, BK=64, 256 threads (8 warps 2m x 4n; warp tile 32x16),
// 2-stage cp.async pipeline, 3 CTAs/SM (64KB smem/CTA).
#define STG 32768u
#define SMEM_BYTES (2 * 32768)

__device__ __forceinline__ void load_stage(uint32_t sb,
                                           const bf16* __restrict__ Ah, const bf16* __restrict__ Al,
                                           const bf16* __restrict__ Wh, const bf16* __restrict__ Wl,
                                           int Kp, int k0, int row0, int col0, int tid) {
#pragma unroll
    for (int it = 0; it < 2; it++) {
        int idx = it * 256 + tid;
        int r = idx >> 3, c = idx & 7;
        uint32_t off = (uint32_t)(r * 128 + ((c ^ (r & 7)) * 16));
        size_t ga = (size_t)(row0 + r) * Kp + k0 + c * 8;
        size_t gw = (size_t)(col0 + r) * Kp + k0 + c * 8;
        cp16(sb + off,          Ah + ga);
        cp16(sb + 8192u + off,  Al + ga);
        cp16(sb + 16384u + off, Wh + gw);
        cp16(sb + 24576u + off, Wl + gw);
    }
}

template <int MODE>
__global__ void __launch_bounds__(256, 3) mma_gemm(
    const bf16* __restrict__ aH, const bf16* __restrict__ aL, int K1p,
    const bf16* __restrict__ a2H, const bf16* __restrict__ a2L, int K2p,
    const bf16* __restrict__ w1H, const bf16* __restrict__ w1L,
    const bf16* __restrict__ w2H, const bf16* __restrict__ w2L,
    const float* __restrict__ b1, const float* __restrict__ b2,
    float* __restrict__ C, int M,
    const float* __restrict__ xtra, bf16* __restrict__ oH, bf16* __restrict__ oL) {
    extern __shared__ __align__(1024) char smem[];
    uint32_t sbase = (uint32_t)__cvta_generic_to_shared(smem);
    int tid = threadIdx.x;
    int lane = tid & 31, wid = tid >> 5;
    int wm = wid & 1, wn = wid >> 1;
    int row0 = blockIdx.y * 64, col0 = blockIdx.x * 64;

    float acc[2][2][4];
#pragma unroll
    for (int m = 0; m < 2; m++)
#pragma unroll
        for (int n = 0; n < 2; n++)
#pragma unroll
            for (int k = 0; k < 4; k++) acc[m][n][k] = 0.f;

    int NC1 = K1p >> 6;
    int NC2 = a2H ? (K2p >> 6) : 0;
    int NC = NC1 + NC2;

    auto seg = [&](int tt, const bf16*& Ah, const bf16*& Al, const bf16*& Wh, const bf16*& Wl,
                   int& Kp, int& k0) {
        if (tt < NC1) { Ah = aH;  Al = aL;  Wh = w1H; Wl = w1L; Kp = K1p; k0 = tt * 64; }
        else          { Ah = a2H; Al = a2L; Wh = w2H; Wl = w2L; Kp = K2p; k0 = (tt - NC1) * 64; }
    };

    // prologue: stage 0
    {
        const bf16 *Ah, *Al, *Wh, *Wl; int Kp, k0;
        seg(0, Ah, Al, Wh, Wl, Kp, k0);
        load_stage(sbase, Ah, Al, Wh, Wl, Kp, k0, row0, col0, tid);
        asm volatile("cp.async.commit_group;");
    }

    for (int ch = 0; ch < NC; ch++) {
        if (ch + 1 < NC) {
            const bf16 *Ah, *Al, *Wh, *Wl; int Kp, k0;
            seg(ch + 1, Ah, Al, Wh, Wl, Kp, k0);
            load_stage(sbase + (uint32_t)((ch + 1) & 1) * STG, Ah, Al, Wh, Wl, Kp, k0, row0, col0, tid);
            asm volatile("cp.async.commit_group;");
            asm volatile("cp.async.wait_group 1;");
        } else {
            asm volatile("cp.async.wait_group 0;");
        }
        __syncthreads();

        uint32_t sb = sbase + (uint32_t)(ch & 1) * STG;
#pragma unroll
        for (int s = 0; s < 4; s++) {
            uint32_t ah[2][4], al[2][4];
#pragma unroll
            for (int m = 0; m < 2; m++) {
                int row = wm * 32 + m * 16 + (lane & 15);
                int chunk = s * 2 + (lane >> 4);
                uint32_t off = (uint32_t)(row * 128 + ((chunk ^ (row & 7)) * 16));
                ldm4(ah[m], sb + off);
                ldm4(al[m], sb + 8192u + off);
            }
            uint32_t bh[4], bl[4];
            {
                int rw = wn * 16 + (lane & 7) + ((lane >> 4) & 1) * 8;
                int chunk = s * 2 + ((lane >> 3) & 1);
                uint32_t off = (uint32_t)(rw * 128 + ((chunk ^ (rw & 7)) * 16));
                ldm4(bh, sb + 16384u + off);
                ldm4(bl, sb + 24576u + off);
            }
#pragma unroll
            for (int m = 0; m < 2; m++)
#pragma unroll
                for (int h = 0; h < 2; h++) {
                    float* cc = acc[m][h];
                    mma16816(cc, ah[m], &bh[h * 2]);
                    mma16816(cc, ah[m], &bl[h * 2]);
                    mma16816(cc, al[m], &bh[h * 2]);
                }
        }
        __syncthreads();
    }

    // epilogue
#pragma unroll
    for (int m = 0; m < 2; m++) {
#pragma unroll
        for (int n = 0; n < 2; n++) {
            float* cc = acc[m][n];
            int r0 = row0 + wm * 32 + m * 16 + (lane >> 2);
            int c0 = col0 + wn * 16 + n * 8 + (lane & 3) * 2;
#pragma unroll
            for (int e = 0; e < 4; e++) {
                int row = r0 + (e >> 1) * 8;
                int col = c0 + (e & 1);
                if (col < M) {
                    float v = cc[e];
                    if (b1) v += __ldg(b1 + col);
                    if (b2) v += __ldg(b2 + col);
                    size_t oidx = (size_t)row * M + col;
                    if (MODE == 0) {
                        C[oidx] = v;
                    } else if (MODE == 1) {
                        C[oidx] = sigm(v);
                    } else {
                        float r = sigm(v) * __ldg(xtra + oidx);
                        split2(r, &oH[oidx], &oL[oidx]);
                    }
                }
            }
        }
    }
}

// ---------------- LSTM pointwise (vectorized: 4 hidden units / thread) ----------------
__global__ void lstm_point(const float* __restrict__ G, const float* __restrict__ st_pair,
                           bf16* __restrict__ hH, bf16* __restrict__ hL,
                           float* __restrict__ out_pair) {
    int idx = blockIdx.x * 256 + threadIdx.x;   // GN*32 groups
    int n = idx >> 5, q = idx & 31;             // j0 = 4q
    const float* g = G + (size_t)n * 512 + 4 * q;
    float4 gi = *reinterpret_cast<const float4*>(g);
    float4 gf = *reinterpret_cast<const float4*>(g + 128);
    float4 gg = *reinterpret_cast<const float4*>(g + 256);
    float4 go = *reinterpret_cast<const float4*>(g + 384);
    const float* sp = st_pair + (size_t)n * 256 + 8 * q;
    float4 s0 = *reinterpret_cast<const float4*>(sp);
    float4 s1 = *reinterpret_cast<const float4*>(sp + 4);
    float cp[4] = {s0.y, s0.w, s1.y, s1.w};
    float vi[4] = {gi.x, gi.y, gi.z, gi.w};
    float vf[4] = {gf.x, gf.y, gf.z, gf.w};
    float vg[4] = {gg.x, gg.y, gg.z, gg.w};
    float vo[4] = {go.x, go.y, go.z, go.w};
    float hn[4], cn[4];
#pragma unroll
    for (int e = 0; e < 4; e++) {
        cn[e] = sigm(vf[e]) * cp[e] + sigm(vi[e]) * tanhf(vg[e]);
        hn[e] = sigm(vo[e]) * tanhf(cn[e]);
    }
    float* op = out_pair + (size_t)n * 256 + 8 * q;
    *reinterpret_cast<float4*>(op)     = make_float4(hn[0], cn[0], hn[1], cn[1]);
    *reinterpret_cast<float4*>(op + 4) = make_float4(hn[2], cn[2], hn[3], cn[3]);
    uint2 H, L;
    split4pack(hn, &H, &L);
    *reinterpret_cast<uint2*>(hH + (size_t)n * 128 + 4 * q) = H;
    *reinterpret_cast<uint2*>(hL + (size_t)n * 128 + 4 * q) = L;
}

// ---------------- extract h from interleaved states -> bf16 hi/lo (vectorized) ----------------
__global__ void extract_h(const float* __restrict__ s1, const float* __restrict__ s2) {
    int idx = blockIdx.x * 256 + threadIdx.x;   // GN*32 groups
    int n = idx >> 5, q = idx & 31;
    size_t base0 = (size_t)n * 256 + 8 * q;
    size_t base1 = ((size_t)GN + n) * 256 + 8 * q;
    size_t ob = (size_t)n * 128 + 4 * q;
    uint2 H, L;
    float h[4];
    float4 a, b;

    a = *reinterpret_cast<const float4*>(s1 + base0);
    b = *reinterpret_cast<const float4*>(s1 + base0 + 4);
    h[0] = a.x; h[1] = a.z; h[2] = b.x; h[3] = b.z;
    split4pack(h, &H, &L);
    *reinterpret_cast<uint2*>(d_h1aH + ob) = H;
    *reinterpret_cast<uint2*>(d_h1aL + ob) = L;

    a = *reinterpret_cast<const float4*>(s1 + base1);
    b = *reinterpret_cast<const float4*>(s1 + base1 + 4);
    h[0] = a.x; h[1] = a.z; h[2] = b.x; h[3] = b.z;
    split4pack(h, &H, &L);
    *reinterpret_cast<uint2*>(d_h2aH + ob) = H;
    *reinterpret_cast<uint2*>(d_h2aL + ob) = L;

    a = *reinterpret_cast<const float4*>(s2 + base0);
    b = *reinterpret_cast<const float4*>(s2 + base0 + 4);
    h[0] = a.x; h[1] = a.z; h[2] = b.x; h[3] = b.z;
    split4pack(h, &H, &L);
    *reinterpret_cast<uint2*>(d_h1bH + ob) = H;
    *reinterpret_cast<uint2*>(d_h1bL + ob) = L;

    a = *reinterpret_cast<const float4*>(s2 + base1);
    b = *reinterpret_cast<const float4*>(s2 + base1 + 4);
    h[0] = a.x; h[1] = a.z; h[2] = b.x; h[3] = b.z;
    split4pack(h, &H, &L);
    *reinterpret_cast<uint2*>(d_h2bH + ob) = H;
    *reinterpret_cast<uint2*>(d_h2bL + ob) = L;
}

// ---------------- layernorm over 256 -> bf16 hi/lo ----------------
__global__ void ln_kernel(const float* __restrict__ enc, const float* __restrict__ gamma,
                          const float* __restrict__ beta,
                          bf16* __restrict__ oH, bf16* __restrict__ oL) {
    int warp = (blockIdx.x * blockDim.x + threadIdx.x) >> 5;
    int lane = threadIdx.x & 31;
    if (warp >= GN) return;
    const float* e = enc + (size_t)warp * EDIM;
    float v[8];
    float s = 0.f;
#pragma unroll
    for (int i = 0; i < 8; i++) { v[i] = e[lane + i * 32]; s += v[i]; }
#pragma unroll
    for (int o = 16; o; o >>= 1) s += __shfl_xor_sync(0xffffffffu, s, o);
    float mean = s * (1.f / 256.f);
    float q = 0.f;
#pragma unroll
    for (int i = 0; i < 8; i++) { float d = v[i] - mean; q += d * d; }
#pragma unroll
    for (int o = 16; o; o >>= 1) q += __shfl_xor_sync(0xffffffffu, q, o);
    float inv = rsqrtf(q * (1.f / 256.f) + 1e-7f);
#pragma unroll
    for (int i = 0; i < 8; i++) {
        int c = lane + i * 32;
        size_t o = (size_t)warp * EDIM + c;
        split2((v[i] - mean) * inv * gamma[c] + beta[c], &oH[o], &oL[o]);
    }
}

// ---------------- host ----------------
static float* symaddr(const void* sym) {
    void* p = nullptr;
    cudaGetSymbolAddress(&p, sym);
    return (float*)p;
}
static bf16* symaddrb(const void* sym) {
    void* p = nullptr;
    cudaGetSymbolAddress(&p, sym);
    return (bf16*)p;
}

extern "C" void kernel_launch(void* const* d_in, const int* in_sizes, int n_in,
                              void* d_out, int out_size) {
    const float* x     = (const float*)d_in[0];
    const float* st1   = (const float*)d_in[1];
    const float* st2   = (const float*)d_in[2];
    const float* wih1  = (const float*)d_in[3];
    const float* whh1  = (const float*)d_in[4];
    const float* bih1  = (const float*)d_in[5];
    const float* bhh1  = (const float*)d_in[6];
    const float* wih2  = (const float*)d_in[7];
    const float* whh2  = (const float*)d_in[8];
    const float* bih2  = (const float*)d_in[9];
    const float* bhh2  = (const float*)d_in[10];
    const float* dw1   = (const float*)d_in[11];
    const float* db1   = (const float*)d_in[12];
    const float* enc_w = (const float*)d_in[13];
    const float* gam   = (const float*)d_in[14];
    const float* bet   = (const float*)d_in[15];
    const float* w2ih1 = (const float*)d_in[16];
    const float* w2hh1 = (const float*)d_in[17];
    const float* b2ih1 = (const float*)d_in[18];
    const float* b2hh1 = (const float*)d_in[19];
    const float* w2ih2 = (const float*)d_in[20];
    const float* w2hh2 = (const float*)d_in[21];
    const float* b2ih2 = (const float*)d_in[22];
    const float* b2hh2 = (const float*)d_in[23];
    const float* dw2   = (const float*)d_in[24];
    const float* db2   = (const float*)d_in[25];
    const float* dec_w = (const float*)d_in[26];

    float* pmag  = symaddr(d_mag);
    float* pcos  = symaddr(d_cosF);
    float* psin  = symaddr(d_sinF);
    float* pG    = symaddr(d_G);
    float* pm1   = symaddr(d_mask1);
    float* penc  = symaddr(d_enc);
    float* psA   = symaddr(d_sscrA);
    float* psB   = symaddr(d_sscrB);

    bf16* magH = symaddrb(d_magH);  bf16* magL = symaddrb(d_magL);
    bf16* y1H  = symaddrb(d_y1H);   bf16* y1L  = symaddrb(d_y1L);
    bf16* enH  = symaddrb(d_encnH); bf16* enL  = symaddrb(d_encnL);
    bf16* muH  = symaddrb(d_mulH);  bf16* muL  = symaddrb(d_mulL);
    bf16* h1aH = symaddrb(d_h1aH);  bf16* h1aL = symaddrb(d_h1aL);
    bf16* h2aH = symaddrb(d_h2aH);  bf16* h2aL = symaddrb(d_h2aL);
    bf16* h1bH = symaddrb(d_h1bH);  bf16* h1bL = symaddrb(d_h1bL);
    bf16* h2bH = symaddrb(d_h2bH);  bf16* h2bL = symaddrb(d_h2bL);
    bf16* hnAH = symaddrb(d_hnAH);  bf16* hnAL = symaddrb(d_hnAL);
    bf16* hnBH = symaddrb(d_hnBH);  bf16* hnBL = symaddrb(d_hnBL);
    bf16* wpH  = symaddrb(d_wpH);   bf16* wpL  = symaddrb(d_wpL);

    cudaFuncSetAttribute((const void*)mma_gemm<0>, cudaFuncAttributeMaxDynamicSharedMemorySize, SMEM_BYTES);
    cudaFuncSetAttribute((const void*)mma_gemm<1>, cudaFuncAttributeMaxDynamicSharedMemorySize, SMEM_BYTES);
    cudaFuncSetAttribute((const void*)mma_gemm<2>, cudaFuncAttributeMaxDynamicSharedMemorySize, SMEM_BYTES);

    float* out = (float*)d_out;
    bool full = (out_size >= 3 * GN * 512);
    float* out_dec = out;
    float* out_s1 = full ? out + (size_t)GN * 512 : psA;
    float* out_s2 = full ? out + (size_t)2 * GN * 512 : psB;

    const int PTV = GN * 32 / 256;  // vectorized pointwise grid (2048)

    init_tw<<<1, 256>>>();

    // fused weight conversion (one launch)
    {
        WConvArgs a;
        const float* s[12] = {wih1, whh1, wih2, whh2, dw1, enc_w, w2ih1, w2hh1, w2ih2, w2hh2, dw2, dec_w};
        int Ms[12]  = {512, 512, 512, 512, 257, 256, 512, 512, 512, 512, 256, 512};
        int Ks[12]  = {FB,  128, 128, 128, 128, 512, 256, 128, 128, 128, 128, 256};
        int Kp[12]  = {320, 128, 128, 128, 128, 512, 256, 128, 128, 128, 128, 256};
        int off[12] = {WP_W1A, WP_W1B, WP_W2A, WP_W2B, WP_DW1, WP_ENC,
                       WP_S1A, WP_S1B, WP_S2A, WP_S2B, WP_DW2, WP_DEC};
        for (int i = 0; i < 12; i++) {
            a.src[i] = s[i]; a.M[i] = Ms[i]; a.K[i] = Ks[i];
            a.Kpad[i] = Kp[i]; a.off[i] = off[i];
        }
        convW_all<<<(WP_TOT + 255) / 256, 256>>>(a);
    }

    fft_fwd<<<GN, 256>>>(x, pmag, pcos, psin, magH, magL);
    extract_h<<<PTV, 256>>>(st1, st2);

    // ---- sep block 1 ----
    mma_gemm<0><<<dim3(8, 256), 256, SMEM_BYTES>>>(
        magH, magL, 320, h1aH, h1aL, 128,
        wpH + WP_W1A, wpL + WP_W1A, wpH + WP_W1B, wpL + WP_W1B,
        bih1, bhh1, pG, 512, nullptr, nullptr, nullptr);
    lstm_point<<<PTV, 256>>>(pG, st1, hnAH, hnAL, out_s1);
    mma_gemm<0><<<dim3(8, 256), 256, SMEM_BYTES>>>(
        hnAH, hnAL, 128, h2aH, h2aL, 128,
        wpH + WP_W2A, wpL + WP_W2A, wpH + WP_W2B, wpL + WP_W2B,
        bih2, bhh2, pG, 512, nullptr, nullptr, nullptr);
    lstm_point<<<PTV, 256>>>(pG, st1 + (size_t)GN * 256, hnBH, hnBL, out_s1 + (size_t)GN * 256);
    mma_gemm<1><<<dim3(5, 256), 256, SMEM_BYTES>>>(
        hnBH, hnBL, 128, nullptr, nullptr, 0,
        wpH + WP_DW1, wpL + WP_DW1, nullptr, nullptr,
        db1, nullptr, pm1, FB, nullptr, nullptr, nullptr);

    // ---- istft + encoder + layernorm ----
    ifft_apply<<<GN, 256>>>(pm1, pmag, pcos, psin, y1H, y1L);
    mma_gemm<0><<<dim3(4, 256), 256, SMEM_BYTES>>>(
        y1H, y1L, 512, nullptr, nullptr, 0,
        wpH + WP_ENC, wpL + WP_ENC, nullptr, nullptr,
        nullptr, nullptr, penc, EDIM, nullptr, nullptr, nullptr);
    ln_kernel<<<GN / 8, 256>>>(penc, gam, bet, enH, enL);

    // ---- sep block 2 ----
    mma_gemm<0><<<dim3(8, 256), 256, SMEM_BYTES>>>(
        enH, enL, 256, h1bH, h1bL, 128,
        wpH + WP_S1A, wpL + WP_S1A, wpH + WP_S1B, wpL + WP_S1B,
        b2ih1, b2hh1, pG, 512, nullptr, nullptr, nullptr);
    lstm_point<<<PTV, 256>>>(pG, st2, hnAH, hnAL, out_s2);
    mma_gemm<0><<<dim3(8, 256), 256, SMEM_BYTES>>>(
        hnAH, hnAL, 128, h2bH, h2bL, 128,
        wpH + WP_S2A, wpL + WP_S2A, wpH + WP_S2B, wpL + WP_S2B,
        b2ih2, b2hh2, pG, 512, nullptr, nullptr, nullptr);
    lstm_point<<<PTV, 256>>>(pG, st2 + (size_t)GN * 256, hnBH, hnBL, out_s2 + (size_t)GN * 256);
    // mask2 GEMM fused with (mask2 * enc) -> bf16 split
    mma_gemm<2><<<dim3(4, 256), 256, SMEM_BYTES>>>(
        hnBH, hnBL, 128, nullptr, nullptr, 0,
        wpH + WP_DW2, wpL + WP_DW2, nullptr, nullptr,
        db2, nullptr, nullptr, EDIM, penc, muH, muL);

    // ---- decode ----
    mma_gemm<0><<<dim3(8, 256), 256, SMEM_BYTES>>>(
        muH, muL, 256, nullptr, nullptr, 0,
        wpH + WP_DEC, wpL + WP_DEC, nullptr, nullptr,
        nullptr, nullptr, out_dec, FDIM, nullptr, nullptr, nullptr);
}